// round 7
// baseline (speedup 1.0000x reference)
#include <cuda_runtime.h>
#include <cuda_bf16.h>
#include <cstdint>

#define DIMC   256
#define INNER  512
#define HEADS  8
#define DHEAD  64
#define WS     7
#define NTOK   49
#define HW     56
#define NPIX   3136      // 56*56, also 49*64
#define BATCH  16
#define NWIN   64        // 8*8 windows

// GEMM smem strides (words) — conflict-free fragment LDS
#define AST 36           // A tile row stride (32 data + 4 pad)
#define BST 136          // B tile row stride (128 data + 8 pad)
#define A_WORDS (128 * AST)   // 4608
#define B_WORDS (32 * BST)    // 4352
#define NSTAGE 3
#define GEMM_SMEM_BYTES ((NSTAGE * (A_WORDS + B_WORDS)) * 4)

// attention smem strides (words)
#define QS_STR 68
#define KS_STR 68
#define VS_STR 72
#define PS_STR 60

// ---------------- scratch (device globals; no allocation allowed) ----------
__device__ __align__(128) float g_y[3L * BATCH * DIMC * NPIX];   // dw+bn out (tf32-rounded)
__device__ __align__(128) float g_qkv[3L * BATCH * INNER * NPIX];// tf32-rounded qkv
__device__ __align__(128) float g_a[(long)BATCH * INNER * NPIX]; // attn out (tf32-rounded)
__device__ __align__(128) float g_w[4L * 131072];                // tf32-rounded weights

// ---------------------------------------------------------------------------
__device__ __forceinline__ uint32_t f2tf32(float x) {
    uint32_t r;
    asm("cvt.rna.tf32.f32 %0, %1;" : "=r"(r) : "f"(x));
    return r;
}

__device__ __forceinline__ void mma_tf32(float4& d, const uint32_t a[4],
                                         const uint32_t b[2], const float4& c) {
    asm volatile(
        "mma.sync.aligned.m16n8k8.row.col.f32.tf32.tf32.f32 "
        "{%0,%1,%2,%3}, {%4,%5,%6,%7}, {%8,%9}, {%10,%11,%12,%13};\n"
        : "=f"(d.x), "=f"(d.y), "=f"(d.z), "=f"(d.w)
        : "r"(a[0]), "r"(a[1]), "r"(a[2]), "r"(a[3]),
          "r"(b[0]), "r"(b[1]),
          "f"(c.x), "f"(c.y), "f"(c.z), "f"(c.w));
}

__device__ __forceinline__ void cpa16(uint32_t dst, const void* src) {
    asm volatile("cp.async.cg.shared.global [%0], [%1], 16;\n"
                 :: "r"(dst), "l"(src));
}
__device__ __forceinline__ void cpa16z(uint32_t dst, const void* src, bool ok) {
    int sz = ok ? 16 : 0;
    asm volatile("cp.async.cg.shared.global [%0], [%1], 16, %2;\n"
                 :: "r"(dst), "l"(src), "r"(sz));
}

// issue one k-tile stage (A 128x32, B 32x128) via cp.async + commit
__device__ __forceinline__ void gemm_stage(const float* __restrict__ A,
                                           const float* __restrict__ B,
                                           int K, int m0, int n0, int k0,
                                           uint32_t sa, uint32_t sb, int tid)
{
    #pragma unroll
    for (int r = 0; r < 4; r++) {
        int idx = tid + r * 256;
        int row = idx >> 3, cc = idx & 7;
        cpa16(sa + (row * AST + cc * 4) * 4,
              &A[(long)(m0 + row) * K + k0 + cc * 4]);
    }
    #pragma unroll
    for (int r = 0; r < 4; r++) {
        int idx = tid + r * 256;
        int row = idx >> 5, cc = idx & 31;
        int n = n0 + cc * 4;
        cpa16z(sb + (row * BST + cc * 4) * 4,
               &B[(long)(k0 + row) * NPIX + n], n < NPIX);
    }
    asm volatile("cp.async.commit_group;\n" ::: "memory");
}

// pipelined tf32 GEMM core
__device__ __forceinline__ void gemm_core(
    const float* __restrict__ A, const float* __restrict__ B,
    int K, int m0, int n0, float* smA, float* smB, float4 acc[4][4])
{
    const int tid = threadIdx.x;
    const int lane = tid & 31, warp = tid >> 5;
    const int wm = warp >> 2, wn = warp & 3;
    const int gi = lane >> 2, li = lane & 3;

    #pragma unroll
    for (int i = 0; i < 4; i++)
        #pragma unroll
        for (int j = 0; j < 4; j++) acc[i][j] = make_float4(0.f, 0.f, 0.f, 0.f);

    uint32_t saB = (uint32_t)__cvta_generic_to_shared(smA);
    uint32_t sbB = (uint32_t)__cvta_generic_to_shared(smB);

    const int nk = K >> 5;
    gemm_stage(A, B, K, m0, n0, 0, saB, sbB, tid);
    gemm_stage(A, B, K, m0, n0, 32, saB + A_WORDS * 4, sbB + B_WORDS * 4, tid);

    for (int kt = 0; kt < nk; kt++) {
        if (kt + 1 < nk)
            asm volatile("cp.async.wait_group 1;\n" ::: "memory");
        else
            asm volatile("cp.async.wait_group 0;\n" ::: "memory");
        __syncthreads();

        const float* As = smA + (kt % NSTAGE) * A_WORDS;
        const float* Bs = smB + (kt % NSTAGE) * B_WORDS;

        #pragma unroll
        for (int ks = 0; ks < 4; ks++) {
            uint32_t bf[4][2];
            #pragma unroll
            for (int j = 0; j < 4; j++) {
                int n = wn * 32 + j * 8 + gi;
                bf[j][0] = __float_as_uint(Bs[(ks * 8 + li) * BST + n]);
                bf[j][1] = __float_as_uint(Bs[(ks * 8 + li + 4) * BST + n]);
            }
            #pragma unroll
            for (int i = 0; i < 4; i++) {
                int rlo = wm * 64 + i * 16 + gi;
                uint32_t af[4];
                af[0] = __float_as_uint(As[rlo * AST + ks * 8 + li]);
                af[1] = __float_as_uint(As[(rlo + 8) * AST + ks * 8 + li]);
                af[2] = __float_as_uint(As[rlo * AST + ks * 8 + li + 4]);
                af[3] = __float_as_uint(As[(rlo + 8) * AST + ks * 8 + li + 4]);
                #pragma unroll
                for (int j = 0; j < 4; j++)
                    mma_tf32(acc[i][j], af, bf[j], acc[i][j]);
            }
        }

        if (kt + 2 < nk) {
            int s = (kt + 2) % NSTAGE;
            gemm_stage(A, B, K, m0, n0, (kt + 2) * 32,
                       saB + s * A_WORDS * 4, sbB + s * B_WORDS * 4, tid);
        }
    }
}

// ---------------------------------------------------------------------------
// Kernel 0: round all weights to tf32 once
// ---------------------------------------------------------------------------
__global__ void prep_w_kernel(const float* __restrict__ pwq,
                              const float* __restrict__ pwk,
                              const float* __restrict__ pwv,
                              const float* __restrict__ wo)
{
    int i = blockIdx.x * 256 + threadIdx.x;
    if (i >= 4 * 131072) return;
    float v;
    if (i < 131072)       v = pwq[i];
    else if (i < 262144)  v = pwk[i - 131072];
    else if (i < 393216)  v = pwv[i - 262144];
    else                  v = wo[i - 393216];
    g_w[i] = __uint_as_float(f2tf32(v));
}

// ---------------------------------------------------------------------------
// Kernel 1: depthwise 3x3 conv + BN, 4 pixels per thread, tf32-rounded out
// ---------------------------------------------------------------------------
__global__ __launch_bounds__(256) void dwbn_kernel(const float* __restrict__ x,
    const float* __restrict__ qdw, const float* __restrict__ qg,
    const float* __restrict__ qb,  const float* __restrict__ qm,
    const float* __restrict__ qv,
    const float* __restrict__ kdw, const float* __restrict__ kg,
    const float* __restrict__ kb,  const float* __restrict__ km,
    const float* __restrict__ kv,
    const float* __restrict__ vdw, const float* __restrict__ vg,
    const float* __restrict__ vb,  const float* __restrict__ vm,
    const float* __restrict__ vv)
{
    const int NSTRIP = NPIX / 4;   // 784
    int idx = blockIdx.x * blockDim.x + threadIdx.x;
    if (idx >= BATCH * DIMC * NSTRIP) return;
    int s = idx % NSTRIP;
    int c = (idx / NSTRIP) % DIMC;
    int b = idx / (NSTRIP * DIMC);
    int p0 = s * 4;
    int yy = p0 / HW, xx0 = p0 % HW;

    float wq[9], wk[9], wv[9];
    #pragma unroll
    for (int t = 0; t < 9; t++) {
        wq[t] = __ldg(&qdw[c * 9 + t]);
        wk[t] = __ldg(&kdw[c * 9 + t]);
        wv[t] = __ldg(&vdw[c * 9 + t]);
    }

    const float* xb = x + ((long)(b * DIMC + c)) * NPIX;
    float aq[4] = {0.f, 0.f, 0.f, 0.f};
    float ak[4] = {0.f, 0.f, 0.f, 0.f};
    float av[4] = {0.f, 0.f, 0.f, 0.f};

    #pragma unroll
    for (int ky = 0; ky < 3; ky++) {
        int iy = yy + ky - 1;
        if (iy < 0 || iy >= HW) continue;
        const float* row = xb + iy * HW;
        float v[6];
        v[0] = (xx0 > 0) ? row[xx0 - 1] : 0.f;
        float4 mid = *(const float4*)&row[xx0];
        v[1] = mid.x; v[2] = mid.y; v[3] = mid.z; v[4] = mid.w;
        v[5] = (xx0 + 4 < HW) ? row[xx0 + 4] : 0.f;
        #pragma unroll
        for (int px = 0; px < 4; px++) {
            #pragma unroll
            for (int kx = 0; kx < 3; kx++) {
                float xv = v[px + kx];
                aq[px] += xv * wq[ky * 3 + kx];
                ak[px] += xv * wk[ky * 3 + kx];
                av[px] += xv * wv[ky * 3 + kx];
            }
        }
    }
    float sq = __ldg(&qg[c]) * rsqrtf(__ldg(&qv[c]) + 1e-5f);
    float sk = __ldg(&kg[c]) * rsqrtf(__ldg(&kv[c]) + 1e-5f);
    float sv = __ldg(&vg[c]) * rsqrtf(__ldg(&vv[c]) + 1e-5f);
    float mq = __ldg(&qm[c]), bq = __ldg(&qb[c]);
    float mk = __ldg(&km[c]), bk = __ldg(&kb[c]);
    float mv = __ldg(&vm[c]), bv = __ldg(&vb[c]);

    long base = ((long)b * DIMC + c) * NPIX + p0;
    const long pstride = (long)BATCH * DIMC * NPIX;
    float4 oq, ok, ov;
    float* oqp = (float*)&oq; float* okp = (float*)&ok; float* ovp = (float*)&ov;
    #pragma unroll
    for (int px = 0; px < 4; px++) {
        oqp[px] = __uint_as_float(f2tf32((aq[px] - mq) * sq + bq));
        okp[px] = __uint_as_float(f2tf32((ak[px] - mk) * sk + bk));
        ovp[px] = __uint_as_float(f2tf32((av[px] - mv) * sv + bv));
    }
    *(float4*)&g_y[base]               = oq;
    *(float4*)&g_y[base + pstride]     = ok;
    *(float4*)&g_y[base + 2 * pstride] = ov;
}

// ---------------------------------------------------------------------------
// Kernel 2: qkv GEMM with coalesced smem-transposed epilogue.
// grid: (25, 4, 48)
// ---------------------------------------------------------------------------
__global__ __launch_bounds__(256) void gemm_qkv_kernel()
{
    extern __shared__ __align__(16) float smem[];
    float* smA = smem;
    float* smB = smem + NSTAGE * A_WORDS;

    int z = blockIdx.z;
    int proj = z >> 4;
    int b = z & 15;
    const float* A = g_w + (long)proj * 131072;          // [512,256] tf32
    const float* B = g_y + ((long)proj * BATCH + b) * DIMC * NPIX;

    int m0 = blockIdx.y * 128;
    int n0 = blockIdx.x * 128;

    float4 acc[4][4];
    gemm_core(A, B, DIMC, m0, n0, smA, smB, acc);

    const int lane = threadIdx.x & 31, warp = threadIdx.x >> 5;
    const int wm = warp >> 2, wn = warp & 3;
    const int gid = lane >> 2, tig = lane & 3;

    // stage C tile transposed: Cs[p][o], stride 132 (LDS.128-friendly)
    __syncthreads();
    float* Cs = smem;
    #pragma unroll
    for (int i = 0; i < 4; i++) {
        int o_lo = wm * 64 + i * 16 + gid;
        int o_hi = o_lo + 8;
        #pragma unroll
        for (int j = 0; j < 4; j++) {
            int p0 = wn * 32 + j * 8 + tig * 2;
            Cs[(p0    ) * 132 + o_lo] = __uint_as_float(f2tf32(acc[i][j].x));
            Cs[(p0 + 1) * 132 + o_lo] = __uint_as_float(f2tf32(acc[i][j].y));
            Cs[(p0    ) * 132 + o_hi] = __uint_as_float(f2tf32(acc[i][j].z));
            Cs[(p0 + 1) * 132 + o_hi] = __uint_as_float(f2tf32(acc[i][j].w));
        }
    }
    __syncthreads();

    // coalesced write: 16 lanes x float4 cover one token's 64 channels
    int h0 = m0 >> 6;
    float* dstb = g_qkv + ((long)proj * BATCH + b) * HEADS * NWIN * NPIX;
    int dd0 = (lane & 15) * 4;
    #pragma unroll
    for (int it = 0; it < 8; it++) {
        int pi = it * 16 + warp * 2 + (lane >> 4);
        int p = n0 + pi;
        if (p < NPIX) {
            int yy = p / HW, xx = p % HW;
            int w = (yy / WS) * 8 + (xx / WS);
            int t = (yy % WS) * WS + (xx % WS);
            #pragma unroll
            for (int hs = 0; hs < 2; hs++) {
                float4 v = *(const float4*)&Cs[pi * 132 + hs * 64 + dd0];
                *(float4*)&dstb[((long)((h0 + hs) * NWIN + w)) * NPIX + t * 64 + dd0] = v;
            }
        }
    }
}

// ---------------------------------------------------------------------------
// Kernel 3: windowed attention on tensor cores; cp.async staging.
// ---------------------------------------------------------------------------
__global__ __launch_bounds__(128) void attn_kernel(const float* __restrict__ pos_emb)
{
    __shared__ __align__(16) uint32_t Qs[64 * QS_STR];
    __shared__ __align__(16) uint32_t Ks[56 * KS_STR];
    __shared__ __align__(16) uint32_t Vs[56 * VS_STR];
    uint32_t* Ps = Qs;

    int w = blockIdx.x, h = blockIdx.y, b = blockIdx.z;
    int tid = threadIdx.x;
    int lane = tid & 31, warp = tid >> 5;
    int gi = lane >> 2, li = lane & 3;

    const long pstride = (long)BATCH * INNER * NPIX;
    long base = (((long)b * HEADS + h) * NWIN + w) * NPIX;
    const float* gq = g_qkv + base;
    const float* gk = g_qkv + base + pstride;
    const float* gv = g_qkv + base + 2 * pstride;

    uint32_t sQ = (uint32_t)__cvta_generic_to_shared(Qs);
    uint32_t sK = (uint32_t)__cvta_generic_to_shared(Ks);
    uint32_t sV = (uint32_t)__cvta_generic_to_shared(Vs);

    for (int i = tid; i < 7 * 64; i += 128) {
        int t = NTOK + (i >> 6), d = i & 63;
        Ks[t * KS_STR + d] = 0;
        Vs[t * VS_STR + d] = 0;
    }
    for (int i = tid; i < NTOK * 16; i += 128) {
        int t = i >> 4, dq = (i & 15) * 4;
        cpa16(sQ + (t * QS_STR + dq) * 4, gq + t * 64 + dq);
        cpa16(sK + (t * KS_STR + dq) * 4, gk + t * 64 + dq);
        cpa16(sV + (t * VS_STR + dq) * 4, gv + t * 64 + dq);
    }
    asm volatile("cp.async.commit_group;\n" ::: "memory");
    asm volatile("cp.async.wait_group 0;\n" ::: "memory");
    __syncthreads();

    int row_lo = warp * 16 + gi;
    int row_hi = row_lo + 8;

    // ---- phase 1: S = Q K^T ----
    uint32_t a[8][4];
    #pragma unroll
    for (int kk = 0; kk < 8; kk++) {
        a[kk][0] = Qs[row_lo * QS_STR + kk * 8 + li];
        a[kk][1] = Qs[row_hi * QS_STR + kk * 8 + li];
        a[kk][2] = Qs[row_lo * QS_STR + kk * 8 + li + 4];
        a[kk][3] = Qs[row_hi * QS_STR + kk * 8 + li + 4];
    }
    float4 c[7];
    #pragma unroll
    for (int j = 0; j < 7; j++) {
        c[j] = make_float4(0.f, 0.f, 0.f, 0.f);
        #pragma unroll
        for (int kk = 0; kk < 8; kk++) {
            uint32_t bf[2];
            bf[0] = Ks[(j * 8 + gi) * KS_STR + kk * 8 + li];
            bf[1] = Ks[(j * 8 + gi) * KS_STR + kk * 8 + li + 4];
            mma_tf32(c[j], a[kk], bf, c[j]);
        }
    }

    // ---- bias + softmax in registers ----
    int rr_lo = row_lo / 7, rc_lo = row_lo % 7;
    int rr_hi = row_hi / 7, rc_hi = row_hi % 7;
    float vlo[14], vhi[14];
    #pragma unroll
    for (int j = 0; j < 7; j++) {
        #pragma unroll
        for (int e = 0; e < 2; e++) {
            int col = j * 8 + li * 2 + e;
            float s_lo = (e == 0) ? c[j].x : c[j].y;
            float s_hi = (e == 0) ? c[j].z : c[j].w;
            if (col < NTOK) {
                int cr = col / 7, cc = col % 7;
                int rel_lo = (cr - rr_lo + 6) * 13 + (cc - rc_lo + 6);
                int rel_hi = (cr - rr_hi + 6) * 13 + (cc - rc_hi + 6);
                rel_lo = min(max(rel_lo, 0), 168);
                rel_hi = min(max(rel_hi, 0), 168);
                vlo[j * 2 + e] = fmaf(s_lo, 0.125f, __ldg(&pos_emb[rel_lo * HEADS + h]));
                vhi[j * 2 + e] = fmaf(s_hi, 0.125f, __ldg(&pos_emb[rel_hi * HEADS + h]));
            } else {
                vlo[j * 2 + e] = -1e30f;
                vhi[j * 2 + e] = -1e30f;
            }
        }
    }
    float mlo = -1e30f, mhi = -1e30f;
    #pragma unroll
    for (int i = 0; i < 14; i++) { mlo = fmaxf(mlo, vlo[i]); mhi = fmaxf(mhi, vhi[i]); }
    mlo = fmaxf(mlo, __shfl_xor_sync(0xffffffffu, mlo, 1));
    mlo = fmaxf(mlo, __shfl_xor_sync(0xffffffffu, mlo, 2));
    mhi = fmaxf(mhi, __shfl_xor_sync(0xffffffffu, mhi, 1));
    mhi = fmaxf(mhi, __shfl_xor_sync(0xffffffffu, mhi, 2));
    float slo = 0.f, shi = 0.f;
    #pragma unroll
    for (int i = 0; i < 14; i++) {
        vlo[i] = __expf(vlo[i] - mlo); slo += vlo[i];
        vhi[i] = __expf(vhi[i] - mhi); shi += vhi[i];
    }
    slo += __shfl_xor_sync(0xffffffffu, slo, 1);
    slo += __shfl_xor_sync(0xffffffffu, slo, 2);
    shi += __shfl_xor_sync(0xffffffffu, shi, 1);
    shi += __shfl_xor_sync(0xffffffffu, shi, 2);
    float ilo = 1.f / slo, ihi = 1.f / shi;

    __syncthreads();
    #pragma unroll
    for (int j = 0; j < 7; j++) {
        #pragma unroll
        for (int e = 0; e < 2; e++) {
            int col = j * 8 + li * 2 + e;
            Ps[row_lo * PS_STR + col] = f2tf32(vlo[j * 2 + e] * ilo);
            Ps[row_hi * PS_STR + col] = f2tf32(vhi[j * 2 + e] * ihi);
        }
    }
    __syncthreads();

    // ---- phase 2: O = P V ----
    uint32_t pa[7][4];
    #pragma unroll
    for (int kk = 0; kk < 7; kk++) {
        pa[kk][0] = Ps[row_lo * PS_STR + kk * 8 + li];
        pa[kk][1] = Ps[row_hi * PS_STR + kk * 8 + li];
        pa[kk][2] = Ps[row_lo * PS_STR + kk * 8 + li + 4];
        pa[kk][3] = Ps[row_hi * PS_STR + kk * 8 + li + 4];
    }
    float* ga = g_a + ((long)b * INNER + h * 64) * NPIX + (long)w * NTOK;
    #pragma unroll
    for (int dn = 0; dn < 8; dn++) {
        float4 o = make_float4(0.f, 0.f, 0.f, 0.f);
        #pragma unroll
        for (int kk = 0; kk < 7; kk++) {
            uint32_t bf[2];
            bf[0] = Vs[(kk * 8 + li) * VS_STR + dn * 8 + gi];
            bf[1] = Vs[(kk * 8 + li + 4) * VS_STR + dn * 8 + gi];
            mma_tf32(o, pa[kk], bf, o);
        }
        int d0 = dn * 8 + li * 2;
        if (row_lo < NTOK) {
            ga[(long)d0 * NPIX + row_lo]       = __uint_as_float(f2tf32(o.x));
            ga[(long)(d0 + 1) * NPIX + row_lo] = __uint_as_float(f2tf32(o.y));
        }
        if (row_hi < NTOK) {
            ga[(long)d0 * NPIX + row_hi]       = __uint_as_float(f2tf32(o.z));
            ga[(long)(d0 + 1) * NPIX + row_hi] = __uint_as_float(f2tf32(o.w));
        }
    }
}

// ---------------------------------------------------------------------------
// Kernel 4: out-projection GEMM + bias with coalesced transposed epilogue.
// grid: (25, 2, 16)
// ---------------------------------------------------------------------------
__global__ __launch_bounds__(256) void gemm_out_kernel(
    const float* __restrict__ ob, float* __restrict__ out)
{
    extern __shared__ __align__(16) float smem[];
    float* smA = smem;
    float* smB = smem + NSTAGE * A_WORDS;

    int b = blockIdx.z;
    const float* A = g_w + 3L * 131072;                  // [256,512] tf32
    const float* B = g_a + (long)b * INNER * NPIX;

    int m0 = blockIdx.y * 128;
    int n0 = blockIdx.x * 128;

    float4 acc[4][4];
    gemm_core(A, B, INNER, m0, n0, smA, smB, acc);

    const int lane = threadIdx.x & 31, warp = threadIdx.x >> 5;
    const int wm = warp >> 2, wn = warp & 3;
    const int gid = lane >> 2, tig = lane & 3;

    // stage C tile transposed: Cs[p][o], stride 131 (131 % 32 == 3, coprime)
    __syncthreads();
    float* Cs = smem;
    #pragma unroll
    for (int i = 0; i < 4; i++) {
        int o_lo = wm * 64 + i * 16 + gid;
        int o_hi = o_lo + 8;
        #pragma unroll
        for (int j = 0; j < 4; j++) {
            int p0 = wn * 32 + j * 8 + tig * 2;
            Cs[(p0    ) * 131 + o_lo] = acc[i][j].x;
            Cs[(p0 + 1) * 131 + o_lo] = acc[i][j].y;
            Cs[(p0    ) * 131 + o_hi] = acc[i][j].z;
            Cs[(p0 + 1) * 131 + o_hi] = acc[i][j].w;
        }
    }
    __syncthreads();

    // lanes = 32 consecutive windowed-p (runs of 7 coalesce), loop over 64 o
    int pi = (warp & 3) * 32 + lane;        // 0..127
    int oh = (warp >> 2) * 64;              // 0 or 64
    int p = n0 + pi;
    if (p < NPIX) {
        int w = p / NTOK, t = p % NTOK;
        int yy = (w / 8) * WS + t / WS;
        int xx = (w % 8) * WS + t % WS;
        long obase = ((long)b * DIMC + m0 + oh) * NPIX + yy * HW + xx;
        const float* crow = &Cs[pi * 131 + oh];
        #pragma unroll 8
        for (int oo = 0; oo < 64; oo++) {
            float bias = __ldg(&ob[m0 + oh + oo]);
            out[obase + (long)oo * NPIX] = crow[oo] + bias;
        }
    }
}

// ---------------------------------------------------------------------------
extern "C" void kernel_launch(void* const* d_in, const int* in_sizes, int n_in,
                              void* d_out, int out_size)
{
    const float* x    = (const float*)d_in[0];
    const float* qdw  = (const float*)d_in[1];
    const float* qg   = (const float*)d_in[2];
    const float* qb   = (const float*)d_in[3];
    const float* qm   = (const float*)d_in[4];
    const float* qv   = (const float*)d_in[5];
    const float* qpw  = (const float*)d_in[6];
    const float* kdw  = (const float*)d_in[7];
    const float* kg   = (const float*)d_in[8];
    const float* kb   = (const float*)d_in[9];
    const float* km   = (const float*)d_in[10];
    const float* kv   = (const float*)d_in[11];
    const float* kpw  = (const float*)d_in[12];
    const float* vdw  = (const float*)d_in[13];
    const float* vg   = (const float*)d_in[14];
    const float* vb   = (const float*)d_in[15];
    const float* vm   = (const float*)d_in[16];
    const float* vv   = (const float*)d_in[17];
    const float* vpw  = (const float*)d_in[18];
    const float* pos  = (const float*)d_in[19];
    const float* outw = (const float*)d_in[20];
    const float* outb = (const float*)d_in[21];
    float* out = (float*)d_out;

    static bool attr_done = false;
    if (!attr_done) {
        cudaFuncSetAttribute(gemm_qkv_kernel,
            cudaFuncAttributeMaxDynamicSharedMemorySize, GEMM_SMEM_BYTES);
        cudaFuncSetAttribute(gemm_out_kernel,
            cudaFuncAttributeMaxDynamicSharedMemorySize, GEMM_SMEM_BYTES);
        attr_done = true;
    }

    prep_w_kernel<<<2048, 256>>>(qpw, kpw, vpw, outw);

    int nstrips = BATCH * DIMC * (NPIX / 4);
    dwbn_kernel<<<(nstrips + 255) / 256, 256>>>(x,
        qdw, qg, qb, qm, qv,
        kdw, kg, kb, km, kv,
        vdw, vg, vb, vm, vv);

    gemm_qkv_kernel<<<dim3(25, 4, 48), 256, GEMM_SMEM_BYTES>>>();

    attn_kernel<<<dim3(NWIN, HEADS, BATCH), 128>>>(pos);

    gemm_out_kernel<<<dim3(25, 2, 16), 256, GEMM_SMEM_BYTES>>>(outb, out);
}

// round 8
// speedup vs baseline: 1.2430x; 1.2430x over previous
#include <cuda_runtime.h>
#include <cuda_bf16.h>
#include <cstdint>

#define DIMC   256
#define INNER  512
#define HEADS  8
#define DHEAD  64
#define WS     7
#define NTOK   49
#define HW     56
#define NPIX   3136      // 56*56, also 49*64
#define BATCH  16
#define NWIN   64        // 8*8 windows

// GEMM smem: A tiles are fragment-permuted (4096 words, no padding needed);
// B tiles row-major padded.
#define BST 136          // B tile row stride (128 data + 8 pad)
#define A_WORDS 4096
#define B_WORDS (32 * BST)    // 4352
#define NSTAGE 3
#define GEMM_SMEM_BYTES ((NSTAGE * (A_WORDS + B_WORDS)) * 4)

// attention smem strides (words)
#define QS_STR 68
#define KS_STR 68
#define VS_STR 72
#define PS_STR 60
#define ATTN_BUF_WORDS (64 * QS_STR + 56 * KS_STR + 56 * VS_STR)  // 12192
#define ATTN_SMEM_BYTES (2 * ATTN_BUF_WORDS * 4)                  // 97536

// ---------------- scratch (device globals; no allocation allowed) ----------
__device__ __align__(128) float g_y[3L * BATCH * DIMC * NPIX];   // dw+bn out (tf32-rounded)
__device__ __align__(128) float g_qkv[3L * BATCH * INNER * NPIX];// tf32-rounded qkv
__device__ __align__(128) float g_a[(long)BATCH * INNER * NPIX]; // attn out (tf32-rounded)
__device__ __align__(128) float g_w[4L * 131072];                // tf32, fragment-permuted

// ---------------------------------------------------------------------------
__device__ __forceinline__ uint32_t f2tf32(float x) {
    uint32_t r;
    asm("cvt.rna.tf32.f32 %0, %1;" : "=r"(r) : "f"(x));
    return r;
}

__device__ __forceinline__ void mma_tf32(float4& d, const uint32_t a[4],
                                         const uint32_t b[2], const float4& c) {
    asm volatile(
        "mma.sync.aligned.m16n8k8.row.col.f32.tf32.tf32.f32 "
        "{%0,%1,%2,%3}, {%4,%5,%6,%7}, {%8,%9}, {%10,%11,%12,%13};\n"
        : "=f"(d.x), "=f"(d.y), "=f"(d.z), "=f"(d.w)
        : "r"(a[0]), "r"(a[1]), "r"(a[2]), "r"(a[3]),
          "r"(b[0]), "r"(b[1]),
          "f"(c.x), "f"(c.y), "f"(c.z), "f"(c.w));
}

__device__ __forceinline__ void cpa16(uint32_t dst, const void* src) {
    asm volatile("cp.async.cg.shared.global [%0], [%1], 16;\n"
                 :: "r"(dst), "l"(src));
}
__device__ __forceinline__ void cpa16z(uint32_t dst, const void* src, bool ok) {
    int sz = ok ? 16 : 0;
    asm volatile("cp.async.cg.shared.global [%0], [%1], 16, %2;\n"
                 :: "r"(dst), "l"(src), "r"(sz));
}

// issue one k-tile stage: A (contiguous permuted 16KB) + B (32x128) + commit
__device__ __forceinline__ void gemm_stage(const float* __restrict__ A,
                                           const float* __restrict__ B,
                                           int K, int m0, int n0, int k0,
                                           uint32_t sa, uint32_t sb, int tid)
{
    const float* Atile = A + ((long)((m0 >> 7) * (K >> 5) + (k0 >> 5))) * A_WORDS;
    #pragma unroll
    for (int r = 0; r < 4; r++) {
        int idx = tid + r * 256;
        cpa16(sa + idx * 16, Atile + idx * 4);
    }
    #pragma unroll
    for (int r = 0; r < 4; r++) {
        int idx = tid + r * 256;
        int row = idx >> 5, cc = idx & 31;
        int n = n0 + cc * 4;
        cpa16z(sb + (row * BST + cc * 4) * 4,
               &B[(long)(k0 + row) * NPIX + n], n < NPIX);
    }
    asm volatile("cp.async.commit_group;\n" ::: "memory");
}

// pipelined tf32 GEMM core; A fragments via single LDS.128 each
__device__ __forceinline__ void gemm_core(
    const float* __restrict__ A, const float* __restrict__ B,
    int K, int m0, int n0, float* smA, float* smB, float4 acc[4][4])
{
    const int tid = threadIdx.x;
    const int lane = tid & 31, warp = tid >> 5;
    const int wm = warp >> 2, wn = warp & 3;
    const int gi = lane >> 2, li = lane & 3;

    #pragma unroll
    for (int i = 0; i < 4; i++)
        #pragma unroll
        for (int j = 0; j < 4; j++) acc[i][j] = make_float4(0.f, 0.f, 0.f, 0.f);

    uint32_t saB = (uint32_t)__cvta_generic_to_shared(smA);
    uint32_t sbB = (uint32_t)__cvta_generic_to_shared(smB);

    const int nk = K >> 5;
    gemm_stage(A, B, K, m0, n0, 0, saB, sbB, tid);
    gemm_stage(A, B, K, m0, n0, 32, saB + A_WORDS * 4, sbB + B_WORDS * 4, tid);

    for (int kt = 0; kt < nk; kt++) {
        if (kt + 1 < nk)
            asm volatile("cp.async.wait_group 1;\n" ::: "memory");
        else
            asm volatile("cp.async.wait_group 0;\n" ::: "memory");
        __syncthreads();

        const float* As = smA + (kt % NSTAGE) * A_WORDS;
        const float* Bs = smB + (kt % NSTAGE) * B_WORDS;
        const uint4* A4 = (const uint4*)As;

        #pragma unroll
        for (int ks = 0; ks < 4; ks++) {
            uint32_t bf[4][2];
            #pragma unroll
            for (int j = 0; j < 4; j++) {
                int n = wn * 32 + j * 8 + gi;
                bf[j][0] = __float_as_uint(Bs[(ks * 8 + li) * BST + n]);
                bf[j][1] = __float_as_uint(Bs[(ks * 8 + li + 4) * BST + n]);
            }
            #pragma unroll
            for (int i = 0; i < 4; i++) {
                uint4 t4 = A4[(ks * 8 + wm * 4 + i) * 32 + lane];
                uint32_t af[4] = {t4.x, t4.y, t4.z, t4.w};
                #pragma unroll
                for (int j = 0; j < 4; j++)
                    mma_tf32(acc[i][j], af, bf[j], acc[i][j]);
            }
        }

        if (kt + 2 < nk) {
            int s = (kt + 2) % NSTAGE;
            gemm_stage(A, B, K, m0, n0, (kt + 2) * 32,
                       saB + s * A_WORDS * 4, sbB + s * B_WORDS * 4, tid);
        }
    }
}

// ---------------------------------------------------------------------------
// Kernel 0: round weights to tf32 AND permute into MMA fragment order.
// tile(mt,kt) of 128x32; word = tile*4096 + (ks*8+matom)*128 + lane*4 + slot
// ---------------------------------------------------------------------------
__global__ void prep_w_kernel(const float* __restrict__ pwq,
                              const float* __restrict__ pwk,
                              const float* __restrict__ pwv,
                              const float* __restrict__ wo)
{
    int i = blockIdx.x * 256 + threadIdx.x;
    if (i >= 4 * 131072) return;
    int seg = i >> 17;
    int j = i & 131071;
    float v;
    if (seg == 0)      v = pwq[j];
    else if (seg == 1) v = pwk[j];
    else if (seg == 2) v = pwv[j];
    else               v = wo[j];
    int K = (seg < 3) ? DIMC : INNER;
    int m = j / K, k = j % K;
    int ntk = K >> 5;
    int ml = m & 127, kl = k & 31;
    long off = (long)seg * 131072
             + ((long)((m >> 7) * ntk + (k >> 5))) * A_WORDS
             + ((kl >> 3) * 8 + (ml >> 4)) * 128
             + ((ml & 7) * 4 + (kl & 3)) * 4
             + ((ml >> 3) & 1) + 2 * ((kl >> 2) & 1);
    g_w[off] = __uint_as_float(f2tf32(v));
}

// ---------------------------------------------------------------------------
// Kernel 1: depthwise 3x3 conv + BN, 4 pixels per thread, tf32-rounded out
// ---------------------------------------------------------------------------
__global__ __launch_bounds__(256) void dwbn_kernel(const float* __restrict__ x,
    const float* __restrict__ qdw, const float* __restrict__ qg,
    const float* __restrict__ qb,  const float* __restrict__ qm,
    const float* __restrict__ qv,
    const float* __restrict__ kdw, const float* __restrict__ kg,
    const float* __restrict__ kb,  const float* __restrict__ km,
    const float* __restrict__ kv,
    const float* __restrict__ vdw, const float* __restrict__ vg,
    const float* __restrict__ vb,  const float* __restrict__ vm,
    const float* __restrict__ vv)
{
    const int NSTRIP = NPIX / 4;   // 784
    int idx = blockIdx.x * blockDim.x + threadIdx.x;
    if (idx >= BATCH * DIMC * NSTRIP) return;
    int s = idx % NSTRIP;
    int c = (idx / NSTRIP) % DIMC;
    int b = idx / (NSTRIP * DIMC);
    int p0 = s * 4;
    int yy = p0 / HW, xx0 = p0 % HW;

    float wq[9], wk[9], wv[9];
    #pragma unroll
    for (int t = 0; t < 9; t++) {
        wq[t] = __ldg(&qdw[c * 9 + t]);
        wk[t] = __ldg(&kdw[c * 9 + t]);
        wv[t] = __ldg(&vdw[c * 9 + t]);
    }

    const float* xb = x + ((long)(b * DIMC + c)) * NPIX;
    float aq[4] = {0.f, 0.f, 0.f, 0.f};
    float ak[4] = {0.f, 0.f, 0.f, 0.f};
    float av[4] = {0.f, 0.f, 0.f, 0.f};

    #pragma unroll
    for (int ky = 0; ky < 3; ky++) {
        int iy = yy + ky - 1;
        if (iy < 0 || iy >= HW) continue;
        const float* row = xb + iy * HW;
        float v[6];
        v[0] = (xx0 > 0) ? row[xx0 - 1] : 0.f;
        float4 mid = *(const float4*)&row[xx0];
        v[1] = mid.x; v[2] = mid.y; v[3] = mid.z; v[4] = mid.w;
        v[5] = (xx0 + 4 < HW) ? row[xx0 + 4] : 0.f;
        #pragma unroll
        for (int px = 0; px < 4; px++) {
            #pragma unroll
            for (int kx = 0; kx < 3; kx++) {
                float xv = v[px + kx];
                aq[px] += xv * wq[ky * 3 + kx];
                ak[px] += xv * wk[ky * 3 + kx];
                av[px] += xv * wv[ky * 3 + kx];
            }
        }
    }
    float sq = __ldg(&qg[c]) * rsqrtf(__ldg(&qv[c]) + 1e-5f);
    float sk = __ldg(&kg[c]) * rsqrtf(__ldg(&kv[c]) + 1e-5f);
    float sv = __ldg(&vg[c]) * rsqrtf(__ldg(&vv[c]) + 1e-5f);
    float mq = __ldg(&qm[c]), bq = __ldg(&qb[c]);
    float mk = __ldg(&km[c]), bk = __ldg(&kb[c]);
    float mv = __ldg(&vm[c]), bv = __ldg(&vb[c]);

    long base = ((long)b * DIMC + c) * NPIX + p0;
    const long pstride = (long)BATCH * DIMC * NPIX;
    float4 oq, ok, ov;
    float* oqp = (float*)&oq; float* okp = (float*)&ok; float* ovp = (float*)&ov;
    #pragma unroll
    for (int px = 0; px < 4; px++) {
        oqp[px] = __uint_as_float(f2tf32((aq[px] - mq) * sq + bq));
        okp[px] = __uint_as_float(f2tf32((ak[px] - mk) * sk + bk));
        ovp[px] = __uint_as_float(f2tf32((av[px] - mv) * sv + bv));
    }
    *(float4*)&g_y[base]               = oq;
    *(float4*)&g_y[base + pstride]     = ok;
    *(float4*)&g_y[base + 2 * pstride] = ov;
}

// ---------------------------------------------------------------------------
// Kernel 2: qkv GEMM (R5 epilogue: scattered windowed store, tf32-rounded)
// grid: (25, 4, 48)
// ---------------------------------------------------------------------------
__global__ __launch_bounds__(256) void gemm_qkv_kernel()
{
    extern __shared__ __align__(16) float smem[];
    float* smA = smem;
    float* smB = smem + NSTAGE * A_WORDS;

    int z = blockIdx.z;
    int proj = z >> 4;
    int b = z & 15;
    const float* A = g_w + (long)proj * 131072;          // permuted [512,256]
    const float* B = g_y + ((long)proj * BATCH + b) * DIMC * NPIX;

    int m0 = blockIdx.y * 128;
    int n0 = blockIdx.x * 128;

    float4 acc[4][4];
    gemm_core(A, B, DIMC, m0, n0, smA, smB, acc);

    const int lane = threadIdx.x & 31, warp = threadIdx.x >> 5;
    const int wm = warp >> 2, wn = warp & 3;
    const int gid = lane >> 2, tig = lane & 3;
    float* dst = g_qkv + ((long)proj * BATCH + b) * HEADS * NWIN * NPIX;

    #pragma unroll
    for (int i = 0; i < 4; i++) {
        int o_lo = m0 + wm * 64 + i * 16 + gid;
        int o_hi = o_lo + 8;
        #pragma unroll
        for (int j = 0; j < 4; j++) {
            int p0 = n0 + wn * 32 + j * 8 + tig * 2;
            int p1 = p0 + 1;
            float vals[4] = {acc[i][j].x, acc[i][j].y, acc[i][j].z, acc[i][j].w};
            int os[4] = {o_lo, o_lo, o_hi, o_hi};
            int ps[4] = {p0, p1, p0, p1};
            #pragma unroll
            for (int e = 0; e < 4; e++) {
                int p = ps[e];
                if (p < NPIX) {
                    int o = os[e];
                    int h = o >> 6, dd = o & 63;
                    int yy = p / HW, xx = p % HW;
                    int w = (yy / WS) * 8 + (xx / WS);
                    int t = (yy % WS) * WS + (xx % WS);
                    dst[((long)(h * NWIN + w)) * NPIX + t * 64 + dd] =
                        __uint_as_float(f2tf32(vals[e]));
                }
            }
        }
    }
}

// ---------------------------------------------------------------------------
// Kernel 3: persistent windowed attention, double-buffered cp.async prefetch.
// grid: (8, HEADS, BATCH); each CTA processes 8 windows.
// ---------------------------------------------------------------------------
__global__ __launch_bounds__(128) void attn_kernel(const float* __restrict__ pos_emb)
{
    extern __shared__ __align__(16) uint32_t abuf[];

    int h = blockIdx.y, b = blockIdx.z;
    int w0 = blockIdx.x * 8;
    int tid = threadIdx.x;
    int lane = tid & 31, warp = tid >> 5;
    int gi = lane >> 2, li = lane & 3;

    const long pstride = (long)BATCH * INNER * NPIX;
    long hb = ((long)b * HEADS + h) * NWIN;

    // zero K/V pad rows in both buffers (cp.async never touches them)
    #pragma unroll
    for (int s = 0; s < 2; s++) {
        uint32_t* Kz = abuf + s * ATTN_BUF_WORDS + 64 * QS_STR;
        uint32_t* Vz = Kz + 56 * KS_STR;
        for (int i = tid; i < 7 * 64; i += 128) {
            int t = NTOK + (i >> 6), d = i & 63;
            Kz[t * KS_STR + d] = 0;
            Vz[t * VS_STR + d] = 0;
        }
    }
    __syncthreads();

    // prefetch window w0 into buffer 0
    {
        long base = (hb + w0) * NPIX;
        const float* gq = g_qkv + base;
        const float* gk = gq + pstride;
        const float* gv = gq + 2 * pstride;
        uint32_t sQ = (uint32_t)__cvta_generic_to_shared(abuf);
        uint32_t sK = sQ + 64 * QS_STR * 4;
        uint32_t sV = sK + 56 * KS_STR * 4;
        for (int i = tid; i < NTOK * 16; i += 128) {
            int t = i >> 4, dq = (i & 15) * 4;
            cpa16(sQ + (t * QS_STR + dq) * 4, gq + t * 64 + dq);
            cpa16(sK + (t * KS_STR + dq) * 4, gk + t * 64 + dq);
            cpa16(sV + (t * VS_STR + dq) * 4, gv + t * 64 + dq);
        }
        asm volatile("cp.async.commit_group;\n" ::: "memory");
    }

    int row_lo = warp * 16 + gi;
    int row_hi = row_lo + 8;
    int rr_lo = row_lo / 7, rc_lo = row_lo % 7;
    int rr_hi = row_hi / 7, rc_hi = row_hi % 7;

    #pragma unroll 1
    for (int it = 0; it < 8; it++) {
        int w = w0 + it;
        uint32_t* Qs = abuf + (it & 1) * ATTN_BUF_WORDS;
        uint32_t* Ks = Qs + 64 * QS_STR;
        uint32_t* Vs = Ks + 56 * KS_STR;
        uint32_t* Ps = Qs;

        asm volatile("cp.async.wait_group 0;\n" ::: "memory");
        __syncthreads();

        // prefetch next window into the other buffer
        if (it < 7) {
            long nb = (hb + w + 1) * NPIX;
            const float* gq = g_qkv + nb;
            const float* gk = gq + pstride;
            const float* gv = gq + 2 * pstride;
            uint32_t sQ = (uint32_t)__cvta_generic_to_shared(
                              abuf + ((it + 1) & 1) * ATTN_BUF_WORDS);
            uint32_t sK = sQ + 64 * QS_STR * 4;
            uint32_t sV = sK + 56 * KS_STR * 4;
            for (int i = tid; i < NTOK * 16; i += 128) {
                int t = i >> 4, dq = (i & 15) * 4;
                cpa16(sQ + (t * QS_STR + dq) * 4, gq + t * 64 + dq);
                cpa16(sK + (t * KS_STR + dq) * 4, gk + t * 64 + dq);
                cpa16(sV + (t * VS_STR + dq) * 4, gv + t * 64 + dq);
            }
            asm volatile("cp.async.commit_group;\n" ::: "memory");
        }

        // ---- phase 1: S = Q K^T ----
        uint32_t a[8][4];
        #pragma unroll
        for (int kk = 0; kk < 8; kk++) {
            a[kk][0] = Qs[row_lo * QS_STR + kk * 8 + li];
            a[kk][1] = Qs[row_hi * QS_STR + kk * 8 + li];
            a[kk][2] = Qs[row_lo * QS_STR + kk * 8 + li + 4];
            a[kk][3] = Qs[row_hi * QS_STR + kk * 8 + li + 4];
        }
        float4 c[7];
        #pragma unroll
        for (int j = 0; j < 7; j++) {
            c[j] = make_float4(0.f, 0.f, 0.f, 0.f);
            #pragma unroll
            for (int kk = 0; kk < 8; kk++) {
                uint32_t bf[2];
                bf[0] = Ks[(j * 8 + gi) * KS_STR + kk * 8 + li];
                bf[1] = Ks[(j * 8 + gi) * KS_STR + kk * 8 + li + 4];
                mma_tf32(c[j], a[kk], bf, c[j]);
            }
        }

        // ---- bias + softmax in registers ----
        float vlo[14], vhi[14];
        #pragma unroll
        for (int j = 0; j < 7; j++) {
            #pragma unroll
            for (int e = 0; e < 2; e++) {
                int col = j * 8 + li * 2 + e;
                float s_lo = (e == 0) ? c[j].x : c[j].y;
                float s_hi = (e == 0) ? c[j].z : c[j].w;
                if (col < NTOK) {
                    int cr = col / 7, cc = col % 7;
                    int rel_lo = (cr - rr_lo + 6) * 13 + (cc - rc_lo + 6);
                    int rel_hi = (cr - rr_hi + 6) * 13 + (cc - rc_hi + 6);
                    rel_lo = min(max(rel_lo, 0), 168);
                    rel_hi = min(max(rel_hi, 0), 168);
                    vlo[j * 2 + e] = fmaf(s_lo, 0.125f, __ldg(&pos_emb[rel_lo * HEADS + h]));
                    vhi[j * 2 + e] = fmaf(s_hi, 0.125f, __ldg(&pos_emb[rel_hi * HEADS + h]));
                } else {
                    vlo[j * 2 + e] = -1e30f;
                    vhi[j * 2 + e] = -1e30f;
                }
            }
        }
        float mlo = -1e30f, mhi = -1e30f;
        #pragma unroll
        for (int i = 0; i < 14; i++) { mlo = fmaxf(mlo, vlo[i]); mhi = fmaxf(mhi, vhi[i]); }
        mlo = fmaxf(mlo, __shfl_xor_sync(0xffffffffu, mlo, 1));
        mlo = fmaxf(mlo, __shfl_xor_sync(0xffffffffu, mlo, 2));
        mhi = fmaxf(mhi, __shfl_xor_sync(0xffffffffu, mhi, 1));
        mhi = fmaxf(mhi, __shfl_xor_sync(0xffffffffu, mhi, 2));
        float slo = 0.f, shi = 0.f;
        #pragma unroll
        for (int i = 0; i < 14; i++) {
            vlo[i] = __expf(vlo[i] - mlo); slo += vlo[i];
            vhi[i] = __expf(vhi[i] - mhi); shi += vhi[i];
        }
        slo += __shfl_xor_sync(0xffffffffu, slo, 1);
        slo += __shfl_xor_sync(0xffffffffu, slo, 2);
        shi += __shfl_xor_sync(0xffffffffu, shi, 1);
        shi += __shfl_xor_sync(0xffffffffu, shi, 2);
        float ilo = 1.f / slo, ihi = 1.f / shi;

        __syncthreads();
        #pragma unroll
        for (int j = 0; j < 7; j++) {
            #pragma unroll
            for (int e = 0; e < 2; e++) {
                int col = j * 8 + li * 2 + e;
                Ps[row_lo * PS_STR + col] = f2tf32(vlo[j * 2 + e] * ilo);
                Ps[row_hi * PS_STR + col] = f2tf32(vhi[j * 2 + e] * ihi);
            }
        }
        __syncthreads();

        // ---- phase 2: O = P V ----
        uint32_t pa[7][4];
        #pragma unroll
        for (int kk = 0; kk < 7; kk++) {
            pa[kk][0] = Ps[row_lo * PS_STR + kk * 8 + li];
            pa[kk][1] = Ps[row_hi * PS_STR + kk * 8 + li];
            pa[kk][2] = Ps[row_lo * PS_STR + kk * 8 + li + 4];
            pa[kk][3] = Ps[row_hi * PS_STR + kk * 8 + li + 4];
        }
        float* ga = g_a + ((long)b * INNER + h * 64) * NPIX + (long)w * NTOK;
        #pragma unroll
        for (int dn = 0; dn < 8; dn++) {
            float4 o = make_float4(0.f, 0.f, 0.f, 0.f);
            #pragma unroll
            for (int kk = 0; kk < 7; kk++) {
                uint32_t bf[2];
                bf[0] = Vs[(kk * 8 + li) * VS_STR + dn * 8 + gi];
                bf[1] = Vs[(kk * 8 + li + 4) * VS_STR + dn * 8 + gi];
                mma_tf32(o, pa[kk], bf, o);
            }
            int d0 = dn * 8 + li * 2;
            if (row_lo < NTOK) {
                ga[(long)d0 * NPIX + row_lo]       = __uint_as_float(f2tf32(o.x));
                ga[(long)(d0 + 1) * NPIX + row_lo] = __uint_as_float(f2tf32(o.y));
            }
            if (row_hi < NTOK) {
                ga[(long)d0 * NPIX + row_hi]       = __uint_as_float(f2tf32(o.z));
                ga[(long)(d0 + 1) * NPIX + row_hi] = __uint_as_float(f2tf32(o.w));
            }
        }
    }
}

// ---------------------------------------------------------------------------
// Kernel 4: out-projection GEMM + bias (R5 scattered epilogue)
// grid: (25, 2, 16)
// ---------------------------------------------------------------------------
__global__ __launch_bounds__(256) void gemm_out_kernel(
    const float* __restrict__ ob, float* __restrict__ out)
{
    extern __shared__ __align__(16) float smem[];
    float* smA = smem;
    float* smB = smem + NSTAGE * A_WORDS;

    int b = blockIdx.z;
    const float* A = g_w + 3L * 131072;                  // permuted [256,512]
    const float* B = g_a + (long)b * INNER * NPIX;

    int m0 = blockIdx.y * 128;
    int n0 = blockIdx.x * 128;

    float4 acc[4][4];
    gemm_core(A, B, INNER, m0, n0, smA, smB, acc);

    const int lane = threadIdx.x & 31, warp = threadIdx.x >> 5;
    const int wm = warp >> 2, wn = warp & 3;
    const int gid = lane >> 2, tig = lane & 3;

    #pragma unroll
    for (int i = 0; i < 4; i++) {
        int o_lo = m0 + wm * 64 + i * 16 + gid;
        int o_hi = o_lo + 8;
        float bias_lo = __ldg(&ob[o_lo]);
        float bias_hi = __ldg(&ob[o_hi]);
        #pragma unroll
        for (int j = 0; j < 4; j++) {
            int p0 = n0 + wn * 32 + j * 8 + tig * 2;
            int p1 = p0 + 1;
            float vals[4] = {acc[i][j].x + bias_lo, acc[i][j].y + bias_lo,
                             acc[i][j].z + bias_hi, acc[i][j].w + bias_hi};
            int os[4] = {o_lo, o_lo, o_hi, o_hi};
            int ps[4] = {p0, p1, p0, p1};
            #pragma unroll
            for (int e = 0; e < 4; e++) {
                int p = ps[e];
                if (p < NPIX) {
                    int o = os[e];
                    int w = p / NTOK, t = p % NTOK;
                    int yy = (w / 8) * WS + t / WS;
                    int xx = (w % 8) * WS + t % WS;
                    out[((long)b * DIMC + o) * NPIX + yy * HW + xx] = vals[e];
                }
            }
        }
    }
}

// ---------------------------------------------------------------------------
extern "C" void kernel_launch(void* const* d_in, const int* in_sizes, int n_in,
                              void* d_out, int out_size)
{
    const float* x    = (const float*)d_in[0];
    const float* qdw  = (const float*)d_in[1];
    const float* qg   = (const float*)d_in[2];
    const float* qb   = (const float*)d_in[3];
    const float* qm   = (const float*)d_in[4];
    const float* qv   = (const float*)d_in[5];
    const float* qpw  = (const float*)d_in[6];
    const float* kdw  = (const float*)d_in[7];
    const float* kg   = (const float*)d_in[8];
    const float* kb   = (const float*)d_in[9];
    const float* km   = (const float*)d_in[10];
    const float* kv   = (const float*)d_in[11];
    const float* kpw  = (const float*)d_in[12];
    const float* vdw  = (const float*)d_in[13];
    const float* vg   = (const float*)d_in[14];
    const float* vb   = (const float*)d_in[15];
    const float* vm   = (const float*)d_in[16];
    const float* vv   = (const float*)d_in[17];
    const float* vpw  = (const float*)d_in[18];
    const float* pos  = (const float*)d_in[19];
    const float* outw = (const float*)d_in[20];
    const float* outb = (const float*)d_in[21];
    float* out = (float*)d_out;

    static bool attr_done = false;
    if (!attr_done) {
        cudaFuncSetAttribute(gemm_qkv_kernel,
            cudaFuncAttributeMaxDynamicSharedMemorySize, GEMM_SMEM_BYTES);
        cudaFuncSetAttribute(gemm_out_kernel,
            cudaFuncAttributeMaxDynamicSharedMemorySize, GEMM_SMEM_BYTES);
        cudaFuncSetAttribute(attn_kernel,
            cudaFuncAttributeMaxDynamicSharedMemorySize, ATTN_SMEM_BYTES);
        attr_done = true;
    }

    prep_w_kernel<<<2048, 256>>>(qpw, kpw, vpw, outw);

    int nstrips = BATCH * DIMC * (NPIX / 4);
    dwbn_kernel<<<(nstrips + 255) / 256, 256>>>(x,
        qdw, qg, qb, qm, qv,
        kdw, kg, kb, km, kv,
        vdw, vg, vb, vm, vv);

    gemm_qkv_kernel<<<dim3(25, 4, 48), 256, GEMM_SMEM_BYTES>>>();

    attn_kernel<<<dim3(8, HEADS, BATCH), 128, ATTN_SMEM_BYTES>>>(pos);

    gemm_out_kernel<<<dim3(25, 2, 16), 256, GEMM_SMEM_BYTES>>>(outb, out);
}

// round 10
// speedup vs baseline: 1.3247x; 1.0657x over previous
#include <cuda_runtime.h>
#include <cuda_bf16.h>
#include <cstdint>

#define DIMC   256
#define INNER  512
#define HEADS  8
#define DHEAD  64
#define WS     7
#define NTOK   49
#define HW     56
#define NPIX   3136      // 56*56, also 49*64
#define BATCH  16
#define NWIN   64        // 8*8 windows

// GEMM smem: A tiles fragment-permuted (4096 words); B row-major padded.
#define BST 136          // B tile row stride (128 data + 8 pad)
#define A_WORDS 4096
#define B_WORDS (32 * BST)    // 4352
#define NSTAGE 3
#define GEMM_SMEM_BYTES ((NSTAGE * (A_WORDS + B_WORDS)) * 4)

// attention smem strides (words)
#define QS_STR 68
#define KS_STR 68
#define VS_STR 72
#define PS_STR 60

// ---------------- scratch (device globals; no allocation allowed) ----------
__device__ __align__(128) float g_y[3L * BATCH * DIMC * NPIX];   // dw+bn out (tf32-rounded)
__device__ __align__(128) float g_qkv[3L * BATCH * INNER * NPIX];// tf32-rounded qkv
__device__ __align__(128) float g_a[(long)BATCH * INNER * NPIX]; // attn out (tf32-rounded)
__device__ __align__(128) float g_w[4L * 131072];                // tf32, fragment-permuted

// ---------------------------------------------------------------------------
__device__ __forceinline__ uint32_t f2tf32(float x) {
    uint32_t r;
    asm("cvt.rna.tf32.f32 %0, %1;" : "=r"(r) : "f"(x));
    return r;
}

__device__ __forceinline__ void mma_tf32(float4& d, const uint32_t a[4],
                                         const uint32_t b[2], const float4& c) {
    asm volatile(
        "mma.sync.aligned.m16n8k8.row.col.f32.tf32.tf32.f32 "
        "{%0,%1,%2,%3}, {%4,%5,%6,%7}, {%8,%9}, {%10,%11,%12,%13};\n"
        : "=f"(d.x), "=f"(d.y), "=f"(d.z), "=f"(d.w)
        : "r"(a[0]), "r"(a[1]), "r"(a[2]), "r"(a[3]),
          "r"(b[0]), "r"(b[1]),
          "f"(c.x), "f"(c.y), "f"(c.z), "f"(c.w));
}

__device__ __forceinline__ void cpa16(uint32_t dst, const void* src) {
    asm volatile("cp.async.cg.shared.global [%0], [%1], 16;\n"
                 :: "r"(dst), "l"(src));
}
__device__ __forceinline__ void cpa16z(uint32_t dst, const void* src, bool ok) {
    int sz = ok ? 16 : 0;
    asm volatile("cp.async.cg.shared.global [%0], [%1], 16, %2;\n"
                 :: "r"(dst), "l"(src), "r"(sz));
}

// issue one k-tile stage: A (contiguous permuted 16KB) + B (32x128) + commit
__device__ __forceinline__ void gemm_stage(const float* __restrict__ A,
                                           const float* __restrict__ B,
                                           int K, int m0, int n0, int k0,
                                           uint32_t sa, uint32_t sb, int tid)
{
    const float* Atile = A + ((long)((m0 >> 7) * (K >> 5) + (k0 >> 5))) * A_WORDS;
    #pragma unroll
    for (int r = 0; r < 4; r++) {
        int idx = tid + r * 256;
        cpa16(sa + idx * 16, Atile + idx * 4);
    }
    #pragma unroll
    for (int r = 0; r < 4; r++) {
        int idx = tid + r * 256;
        int row = idx >> 5, cc = idx & 31;
        int n = n0 + cc * 4;
        cpa16z(sb + (row * BST + cc * 4) * 4,
               &B[(long)(k0 + row) * NPIX + n], n < NPIX);
    }
    asm volatile("cp.async.commit_group;\n" ::: "memory");
}

// pipelined tf32 GEMM core; A fragments via single LDS.128 each
__device__ __forceinline__ void gemm_core(
    const float* __restrict__ A, const float* __restrict__ B,
    int K, int m0, int n0, float* smA, float* smB, float4 acc[4][4])
{
    const int tid = threadIdx.x;
    const int lane = tid & 31, warp = tid >> 5;
    const int wm = warp >> 2, wn = warp & 3;
    const int gi = lane >> 2, li = lane & 3;

    #pragma unroll
    for (int i = 0; i < 4; i++)
        #pragma unroll
        for (int j = 0; j < 4; j++) acc[i][j] = make_float4(0.f, 0.f, 0.f, 0.f);

    uint32_t saB = (uint32_t)__cvta_generic_to_shared(smA);
    uint32_t sbB = (uint32_t)__cvta_generic_to_shared(smB);

    const int nk = K >> 5;
    gemm_stage(A, B, K, m0, n0, 0, saB, sbB, tid);
    gemm_stage(A, B, K, m0, n0, 32, saB + A_WORDS * 4, sbB + B_WORDS * 4, tid);

    for (int kt = 0; kt < nk; kt++) {
        if (kt + 1 < nk)
            asm volatile("cp.async.wait_group 1;\n" ::: "memory");
        else
            asm volatile("cp.async.wait_group 0;\n" ::: "memory");
        __syncthreads();

        const float* Bs = smB + (kt % NSTAGE) * B_WORDS;
        const uint4* A4 = (const uint4*)(smA + (kt % NSTAGE) * A_WORDS);

        #pragma unroll
        for (int ks = 0; ks < 4; ks++) {
            uint32_t bf[4][2];
            #pragma unroll
            for (int j = 0; j < 4; j++) {
                int n = wn * 32 + j * 8 + gi;
                bf[j][0] = __float_as_uint(Bs[(ks * 8 + li) * BST + n]);
                bf[j][1] = __float_as_uint(Bs[(ks * 8 + li + 4) * BST + n]);
            }
            #pragma unroll
            for (int i = 0; i < 4; i++) {
                uint4 t4 = A4[(ks * 8 + wm * 4 + i) * 32 + lane];
                uint32_t af[4] = {t4.x, t4.y, t4.z, t4.w};
                #pragma unroll
                for (int j = 0; j < 4; j++)
                    mma_tf32(acc[i][j], af, bf[j], acc[i][j]);
            }
        }

        if (kt + 2 < nk) {
            int s = (kt + 2) % NSTAGE;
            gemm_stage(A, B, K, m0, n0, (kt + 2) * 32,
                       saB + s * A_WORDS * 4, sbB + s * B_WORDS * 4, tid);
        }
    }
}

// ---------------------------------------------------------------------------
// Kernel 0: round weights to tf32 AND permute into MMA fragment order.
// ---------------------------------------------------------------------------
__global__ void prep_w_kernel(const float* __restrict__ pwq,
                              const float* __restrict__ pwk,
                              const float* __restrict__ pwv,
                              const float* __restrict__ wo)
{
    int i = blockIdx.x * 256 + threadIdx.x;
    if (i >= 4 * 131072) return;
    int seg = i >> 17;
    int j = i & 131071;
    float v;
    if (seg == 0)      v = pwq[j];
    else if (seg == 1) v = pwk[j];
    else if (seg == 2) v = pwv[j];
    else               v = wo[j];
    int K = (seg < 3) ? DIMC : INNER;
    int m = j / K, k = j % K;
    int ntk = K >> 5;
    int ml = m & 127, kl = k & 31;
    long off = (long)seg * 131072
             + ((long)((m >> 7) * ntk + (k >> 5))) * A_WORDS
             + ((kl >> 3) * 8 + (ml >> 4)) * 128
             + ((ml & 7) * 4 + (kl & 3)) * 4
             + ((ml >> 3) & 1) + 2 * ((kl >> 2) & 1);
    g_w[off] = __uint_as_float(f2tf32(v));
}

// ---------------------------------------------------------------------------
// Kernel 1: depthwise 3x3 conv + BN, 4 pixels per thread, tf32-rounded out
// ---------------------------------------------------------------------------
__global__ __launch_bounds__(256) void dwbn_kernel(const float* __restrict__ x,
    const float* __restrict__ qdw, const float* __restrict__ qg,
    const float* __restrict__ qb,  const float* __restrict__ qm,
    const float* __restrict__ qv,
    const float* __restrict__ kdw, const float* __restrict__ kg,
    const float* __restrict__ kb,  const float* __restrict__ km,
    const float* __restrict__ kv,
    const float* __restrict__ vdw, const float* __restrict__ vg,
    const float* __restrict__ vb,  const float* __restrict__ vm,
    const float* __restrict__ vv)
{
    const int NSTRIP = NPIX / 4;   // 784
    int idx = blockIdx.x * blockDim.x + threadIdx.x;
    if (idx >= BATCH * DIMC * NSTRIP) return;
    int s = idx % NSTRIP;
    int c = (idx / NSTRIP) % DIMC;
    int b = idx / (NSTRIP * DIMC);
    int p0 = s * 4;
    int yy = p0 / HW, xx0 = p0 % HW;

    float wq[9], wk[9], wv[9];
    #pragma unroll
    for (int t = 0; t < 9; t++) {
        wq[t] = __ldg(&qdw[c * 9 + t]);
        wk[t] = __ldg(&kdw[c * 9 + t]);
        wv[t] = __ldg(&vdw[c * 9 + t]);
    }

    const float* xb = x + ((long)(b * DIMC + c)) * NPIX;
    float aq[4] = {0.f, 0.f, 0.f, 0.f};
    float ak[4] = {0.f, 0.f, 0.f, 0.f};
    float av[4] = {0.f, 0.f, 0.f, 0.f};

    #pragma unroll
    for (int ky = 0; ky < 3; ky++) {
        int iy = yy + ky - 1;
        if (iy < 0 || iy >= HW) continue;
        const float* row = xb + iy * HW;
        float v[6];
        v[0] = (xx0 > 0) ? row[xx0 - 1] : 0.f;
        float4 mid = *(const float4*)&row[xx0];
        v[1] = mid.x; v[2] = mid.y; v[3] = mid.z; v[4] = mid.w;
        v[5] = (xx0 + 4 < HW) ? row[xx0 + 4] : 0.f;
        #pragma unroll
        for (int px = 0; px < 4; px++) {
            #pragma unroll
            for (int kx = 0; kx < 3; kx++) {
                float xv = v[px + kx];
                aq[px] += xv * wq[ky * 3 + kx];
                ak[px] += xv * wk[ky * 3 + kx];
                av[px] += xv * wv[ky * 3 + kx];
            }
        }
    }
    float sq = __ldg(&qg[c]) * rsqrtf(__ldg(&qv[c]) + 1e-5f);
    float sk = __ldg(&kg[c]) * rsqrtf(__ldg(&kv[c]) + 1e-5f);
    float sv = __ldg(&vg[c]) * rsqrtf(__ldg(&vv[c]) + 1e-5f);
    float mq = __ldg(&qm[c]), bq = __ldg(&qb[c]);
    float mk = __ldg(&km[c]), bk = __ldg(&kb[c]);
    float mv = __ldg(&vm[c]), bv = __ldg(&vb[c]);

    long base = ((long)b * DIMC + c) * NPIX + p0;
    const long pstride = (long)BATCH * DIMC * NPIX;
    float4 oq, ok, ov;
    float* oqp = (float*)&oq; float* okp = (float*)&ok; float* ovp = (float*)&ov;
    #pragma unroll
    for (int px = 0; px < 4; px++) {
        oqp[px] = __uint_as_float(f2tf32((aq[px] - mq) * sq + bq));
        okp[px] = __uint_as_float(f2tf32((ak[px] - mk) * sk + bk));
        ovp[px] = __uint_as_float(f2tf32((av[px] - mv) * sv + bv));
    }
    *(float4*)&g_y[base]               = oq;
    *(float4*)&g_y[base + pstride]     = ok;
    *(float4*)&g_y[base + 2 * pstride] = ov;
}

// ---------------------------------------------------------------------------
// Kernel 2: qkv GEMM (scattered windowed store, tf32-rounded)
// grid: (25, 4, 48)
// ---------------------------------------------------------------------------
__global__ __launch_bounds__(256) void gemm_qkv_kernel()
{
    extern __shared__ __align__(16) float smem[];
    float* smA = smem;
    float* smB = smem + NSTAGE * A_WORDS;

    int z = blockIdx.z;
    int proj = z >> 4;
    int b = z & 15;
    const float* A = g_w + (long)proj * 131072;          // permuted [512,256]
    const float* B = g_y + ((long)proj * BATCH + b) * DIMC * NPIX;

    int m0 = blockIdx.y * 128;
    int n0 = blockIdx.x * 128;

    float4 acc[4][4];
    gemm_core(A, B, DIMC, m0, n0, smA, smB, acc);

    const int lane = threadIdx.x & 31, warp = threadIdx.x >> 5;
    const int wm = warp >> 2, wn = warp & 3;
    const int gid = lane >> 2, tig = lane & 3;
    float* dst = g_qkv + ((long)proj * BATCH + b) * HEADS * NWIN * NPIX;

    #pragma unroll
    for (int i = 0; i < 4; i++) {
        int o_lo = m0 + wm * 64 + i * 16 + gid;
        int o_hi = o_lo + 8;
        #pragma unroll
        for (int j = 0; j < 4; j++) {
            int p0 = n0 + wn * 32 + j * 8 + tig * 2;
            int p1 = p0 + 1;
            float vals[4] = {acc[i][j].x, acc[i][j].y, acc[i][j].z, acc[i][j].w};
            int os[4] = {o_lo, o_lo, o_hi, o_hi};
            int ps[4] = {p0, p1, p0, p1};
            #pragma unroll
            for (int e = 0; e < 4; e++) {
                int p = ps[e];
                if (p < NPIX) {
                    int o = os[e];
                    int h = o >> 6, dd = o & 63;
                    int yy = p / HW, xx = p % HW;
                    int w = (yy / WS) * 8 + (xx / WS);
                    int t = (yy % WS) * WS + (xx % WS);
                    dst[((long)(h * NWIN + w)) * NPIX + t * 64 + dd] =
                        __uint_as_float(f2tf32(vals[e]));
                }
            }
        }
    }
}

// ---------------------------------------------------------------------------
// Kernel 3: windowed attention, cp.async staging with split Q+K / V groups.
// grid: (NWIN, HEADS, BATCH), 128 threads.
// ---------------------------------------------------------------------------
__global__ __launch_bounds__(128) void attn_kernel(const float* __restrict__ pos_emb)
{
    __shared__ __align__(16) uint32_t Qs[64 * QS_STR];
    __shared__ __align__(16) uint32_t Ks[56 * KS_STR];
    __shared__ __align__(16) uint32_t Vs[56 * VS_STR];
    uint32_t* Ps = Qs;

    int w = blockIdx.x, h = blockIdx.y, b = blockIdx.z;
    int tid = threadIdx.x;
    int lane = tid & 31, warp = tid >> 5;
    int gi = lane >> 2, li = lane & 3;

    const long pstride = (long)BATCH * INNER * NPIX;
    long base = (((long)b * HEADS + h) * NWIN + w) * NPIX;
    const float* gq = g_qkv + base;
    const float* gk = g_qkv + base + pstride;
    const float* gv = g_qkv + base + 2 * pstride;

    uint32_t sQ = (uint32_t)__cvta_generic_to_shared(Qs);
    uint32_t sK = (uint32_t)__cvta_generic_to_shared(Ks);
    uint32_t sV = (uint32_t)__cvta_generic_to_shared(Vs);

    for (int i = tid; i < 7 * 64; i += 128) {
        int t = NTOK + (i >> 6), d = i & 63;
        Ks[t * KS_STR + d] = 0;
        Vs[t * VS_STR + d] = 0;
    }
    // group 0: Q + K
    for (int i = tid; i < NTOK * 16; i += 128) {
        int t = i >> 4, dq = (i & 15) * 4;
        cpa16(sQ + (t * QS_STR + dq) * 4, gq + t * 64 + dq);
        cpa16(sK + (t * KS_STR + dq) * 4, gk + t * 64 + dq);
    }
    asm volatile("cp.async.commit_group;\n" ::: "memory");
    // group 1: V
    for (int i = tid; i < NTOK * 16; i += 128) {
        int t = i >> 4, dq = (i & 15) * 4;
        cpa16(sV + (t * VS_STR + dq) * 4, gv + t * 64 + dq);
    }
    asm volatile("cp.async.commit_group;\n" ::: "memory");

    // wait for Q+K only; V continues in flight
    asm volatile("cp.async.wait_group 1;\n" ::: "memory");
    __syncthreads();

    int row_lo = warp * 16 + gi;
    int row_hi = row_lo + 8;

    // ---- phase 1: S = Q K^T ----
    uint32_t a[8][4];
    #pragma unroll
    for (int kk = 0; kk < 8; kk++) {
        a[kk][0] = Qs[row_lo * QS_STR + kk * 8 + li];
        a[kk][1] = Qs[row_hi * QS_STR + kk * 8 + li];
        a[kk][2] = Qs[row_lo * QS_STR + kk * 8 + li + 4];
        a[kk][3] = Qs[row_hi * QS_STR + kk * 8 + li + 4];
    }
    float4 c[7];
    #pragma unroll
    for (int j = 0; j < 7; j++) {
        c[j] = make_float4(0.f, 0.f, 0.f, 0.f);
        #pragma unroll
        for (int kk = 0; kk < 8; kk++) {
            uint32_t bf[2];
            bf[0] = Ks[(j * 8 + gi) * KS_STR + kk * 8 + li];
            bf[1] = Ks[(j * 8 + gi) * KS_STR + kk * 8 + li + 4];
            mma_tf32(c[j], a[kk], bf, c[j]);
        }
    }

    // ---- bias + softmax in registers ----
    int rr_lo = row_lo / 7, rc_lo = row_lo % 7;
    int rr_hi = row_hi / 7, rc_hi = row_hi % 7;
    float vlo[14], vhi[14];
    #pragma unroll
    for (int j = 0; j < 7; j++) {
        #pragma unroll
        for (int e = 0; e < 2; e++) {
            int col = j * 8 + li * 2 + e;
            float s_lo = (e == 0) ? c[j].x : c[j].y;
            float s_hi = (e == 0) ? c[j].z : c[j].w;
            if (col < NTOK) {
                int cr = col / 7, cc = col % 7;
                int rel_lo = (cr - rr_lo + 6) * 13 + (cc - rc_lo + 6);
                int rel_hi = (cr - rr_hi + 6) * 13 + (cc - rc_hi + 6);
                rel_lo = min(max(rel_lo, 0), 168);
                rel_hi = min(max(rel_hi, 0), 168);
                vlo[j * 2 + e] = fmaf(s_lo, 0.125f, __ldg(&pos_emb[rel_lo * HEADS + h]));
                vhi[j * 2 + e] = fmaf(s_hi, 0.125f, __ldg(&pos_emb[rel_hi * HEADS + h]));
            } else {
                vlo[j * 2 + e] = -1e30f;
                vhi[j * 2 + e] = -1e30f;
            }
        }
    }
    float mlo = -1e30f, mhi = -1e30f;
    #pragma unroll
    for (int i = 0; i < 14; i++) { mlo = fmaxf(mlo, vlo[i]); mhi = fmaxf(mhi, vhi[i]); }
    mlo = fmaxf(mlo, __shfl_xor_sync(0xffffffffu, mlo, 1));
    mlo = fmaxf(mlo, __shfl_xor_sync(0xffffffffu, mlo, 2));
    mhi = fmaxf(mhi, __shfl_xor_sync(0xffffffffu, mhi, 1));
    mhi = fmaxf(mhi, __shfl_xor_sync(0xffffffffu, mhi, 2));
    float slo = 0.f, shi = 0.f;
    #pragma unroll
    for (int i = 0; i < 14; i++) {
        vlo[i] = __expf(vlo[i] - mlo); slo += vlo[i];
        vhi[i] = __expf(vhi[i] - mhi); shi += vhi[i];
    }
    slo += __shfl_xor_sync(0xffffffffu, slo, 1);
    slo += __shfl_xor_sync(0xffffffffu, slo, 2);
    shi += __shfl_xor_sync(0xffffffffu, shi, 1);
    shi += __shfl_xor_sync(0xffffffffu, shi, 2);
    float ilo = 1.f / slo, ihi = 1.f / shi;

    // ensure V landed (almost always already done) and Qs reads complete
    asm volatile("cp.async.wait_group 0;\n" ::: "memory");
    __syncthreads();
    #pragma unroll
    for (int j = 0; j < 7; j++) {
        #pragma unroll
        for (int e = 0; e < 2; e++) {
            int col = j * 8 + li * 2 + e;
            Ps[row_lo * PS_STR + col] = f2tf32(vlo[j * 2 + e] * ilo);
            Ps[row_hi * PS_STR + col] = f2tf32(vhi[j * 2 + e] * ihi);
        }
    }
    __syncthreads();

    // ---- phase 2: O = P V ----
    uint32_t pa[7][4];
    #pragma unroll
    for (int kk = 0; kk < 7; kk++) {
        pa[kk][0] = Ps[row_lo * PS_STR + kk * 8 + li];
        pa[kk][1] = Ps[row_hi * PS_STR + kk * 8 + li];
        pa[kk][2] = Ps[row_lo * PS_STR + kk * 8 + li + 4];
        pa[kk][3] = Ps[row_hi * PS_STR + kk * 8 + li + 4];
    }
    float* ga = g_a + ((long)b * INNER + h * 64) * NPIX + (long)w * NTOK;
    #pragma unroll
    for (int dn = 0; dn < 8; dn++) {
        float4 o = make_float4(0.f, 0.f, 0.f, 0.f);
        #pragma unroll
        for (int kk = 0; kk < 7; kk++) {
            uint32_t bf[2];
            bf[0] = Vs[(kk * 8 + li) * VS_STR + dn * 8 + gi];
            bf[1] = Vs[(kk * 8 + li + 4) * VS_STR + dn * 8 + gi];
            mma_tf32(o, pa[kk], bf, o);
        }
        int d0 = dn * 8 + li * 2;
        if (row_lo < NTOK) {
            ga[(long)d0 * NPIX + row_lo]       = __uint_as_float(f2tf32(o.x));
            ga[(long)(d0 + 1) * NPIX + row_lo] = __uint_as_float(f2tf32(o.y));
        }
        if (row_hi < NTOK) {
            ga[(long)d0 * NPIX + row_hi]       = __uint_as_float(f2tf32(o.z));
            ga[(long)(d0 + 1) * NPIX + row_hi] = __uint_as_float(f2tf32(o.w));
        }
    }
}

// ---------------------------------------------------------------------------
// Kernel 4: out-projection GEMM + bias (scattered epilogue)
// grid: (25, 2, 16)
// ---------------------------------------------------------------------------
__global__ __launch_bounds__(256) void gemm_out_kernel(
    const float* __restrict__ ob, float* __restrict__ out)
{
    extern __shared__ __align__(16) float smem[];
    float* smA = smem;
    float* smB = smem + NSTAGE * A_WORDS;

    int b = blockIdx.z;
    const float* A = g_w + 3L * 131072;                  // permuted [256,512]
    const float* B = g_a + (long)b * INNER * NPIX;

    int m0 = blockIdx.y * 128;
    int n0 = blockIdx.x * 128;

    float4 acc[4][4];
    gemm_core(A, B, INNER, m0, n0, smA, smB, acc);

    const int lane = threadIdx.x & 31, warp = threadIdx.x >> 5;
    const int wm = warp >> 2, wn = warp & 3;
    const int gid = lane >> 2, tig = lane & 3;

    #pragma unroll
    for (int i = 0; i < 4; i++) {
        int o_lo = m0 + wm * 64 + i * 16 + gid;
        int o_hi = o_lo + 8;
        float bias_lo = __ldg(&ob[o_lo]);
        float bias_hi = __ldg(&ob[o_hi]);
        #pragma unroll
        for (int j = 0; j < 4; j++) {
            int p0 = n0 + wn * 32 + j * 8 + tig * 2;
            int p1 = p0 + 1;
            float vals[4] = {acc[i][j].x + bias_lo, acc[i][j].y + bias_lo,
                             acc[i][j].z + bias_hi, acc[i][j].w + bias_hi};
            int os[4] = {o_lo, o_lo, o_hi, o_hi};
            int ps[4] = {p0, p1, p0, p1};
            #pragma unroll
            for (int e = 0; e < 4; e++) {
                int p = ps[e];
                if (p < NPIX) {
                    int o = os[e];
                    int w = p / NTOK, t = p % NTOK;
                    int yy = (w / 8) * WS + t / WS;
                    int xx = (w % 8) * WS + t % WS;
                    out[((long)b * DIMC + o) * NPIX + yy * HW + xx] = vals[e];
                }
            }
        }
    }
}

// ---------------------------------------------------------------------------
extern "C" void kernel_launch(void* const* d_in, const int* in_sizes, int n_in,
                              void* d_out, int out_size)
{
    const float* x    = (const float*)d_in[0];
    const float* qdw  = (const float*)d_in[1];
    const float* qg   = (const float*)d_in[2];
    const float* qb   = (const float*)d_in[3];
    const float* qm   = (const float*)d_in[4];
    const float* qv   = (const float*)d_in[5];
    const float* qpw  = (const float*)d_in[6];
    const float* kdw  = (const float*)d_in[7];
    const float* kg   = (const float*)d_in[8];
    const float* kb   = (const float*)d_in[9];
    const float* km   = (const float*)d_in[10];
    const float* kv   = (const float*)d_in[11];
    const float* kpw  = (const float*)d_in[12];
    const float* vdw  = (const float*)d_in[13];
    const float* vg   = (const float*)d_in[14];
    const float* vb   = (const float*)d_in[15];
    const float* vm   = (const float*)d_in[16];
    const float* vv   = (const float*)d_in[17];
    const float* vpw  = (const float*)d_in[18];
    const float* pos  = (const float*)d_in[19];
    const float* outw = (const float*)d_in[20];
    const float* outb = (const float*)d_in[21];
    float* out = (float*)d_out;

    static bool attr_done = false;
    if (!attr_done) {
        cudaFuncSetAttribute(gemm_qkv_kernel,
            cudaFuncAttributeMaxDynamicSharedMemorySize, GEMM_SMEM_BYTES);
        cudaFuncSetAttribute(gemm_out_kernel,
            cudaFuncAttributeMaxDynamicSharedMemorySize, GEMM_SMEM_BYTES);
        attr_done = true;
    }

    prep_w_kernel<<<2048, 256>>>(qpw, kpw, vpw, outw);

    int nstrips = BATCH * DIMC * (NPIX / 4);
    dwbn_kernel<<<(nstrips + 255) / 256, 256>>>(x,
        qdw, qg, qb, qm, qv,
        kdw, kg, kb, km, kv,
        vdw, vg, vb, vm, vv);

    gemm_qkv_kernel<<<dim3(25, 4, 48), 256, GEMM_SMEM_BYTES>>>();

    attn_kernel<<<dim3(NWIN, HEADS, BATCH), 128>>>(pos);

    gemm_out_kernel<<<dim3(25, 2, 16), 256, GEMM_SMEM_BYTES>>>(outb, out);
}

// round 14
// speedup vs baseline: 1.4511x; 1.0954x over previous
#include <cuda_runtime.h>
#include <cuda_fp16.h>
#include <cstdint>

#define DIMC   256
#define INNER  512
#define HEADS  8
#define DHEAD  64
#define WS     7
#define NTOK   49
#define HW     56
#define NPIX   3136      // 56*56
#define BATCH  16
#define NWIN   64        // 8*8 windows

// ---- fp16 GEMM smem geometry (in 4-byte words = half2 units) ----
#define BST2   136                 // B tile row stride (128 data + 8 pad)
#define A_W2   2048                // A tile: 128m x 32k fp16 = 8KB
#define B_W2   (16 * BST2)         // 2176 words
#define NSTAGE 3
#define GEMM_SMEM_BYTES ((NSTAGE * (A_W2 + B_W2)) * 4)   // 50688

// ---- attn smem strides (half2 words) ----
#define QST2 36
#define KST2 36
#define VST2 28

// ---------------- scratch (device globals) ----------------
// dw+bn out, fp16, channel-pair interleaved: [proj][b][c>>1][p][2]
__device__ __align__(128) __half g_yh[3L * BATCH * DIMC * NPIX];
// Q,K fp16: [proj(2)][b][h][w][t*64+d]
__device__ __align__(128) __half g_qkvh[2L * BATCH * INNER * NPIX];
// V fp16 transposed: [b][h][w][d][56]  (t in 0..55, only t<49 written)
__device__ __align__(128) __half g_vT[(long)BATCH * HEADS * NWIN * DHEAD * 56];
// attn out fp16, pair interleaved: [b][c>>1][p][2]
__device__ __align__(128) __half g_ah[(long)BATCH * INNER * NPIX];
// weights fp16, MMA-fragment permuted
__device__ __align__(128) __half g_wh[4L * 131072];

// ---------------------------------------------------------------------------
__device__ __forceinline__ void mma_f16(float4& d,
    uint32_t a0, uint32_t a1, uint32_t a2, uint32_t a3,
    uint32_t b0, uint32_t b1, const float4& c)
{
    asm volatile(
        "mma.sync.aligned.m16n8k16.row.col.f32.f16.f16.f32 "
        "{%0,%1,%2,%3}, {%4,%5,%6,%7}, {%8,%9}, {%10,%11,%12,%13};\n"
        : "=f"(d.x), "=f"(d.y), "=f"(d.z), "=f"(d.w)
        : "r"(a0), "r"(a1), "r"(a2), "r"(a3), "r"(b0), "r"(b1),
          "f"(c.x), "f"(c.y), "f"(c.z), "f"(c.w));
}

__device__ __forceinline__ void cpa16(uint32_t dst, const void* src) {
    asm volatile("cp.async.cg.shared.global [%0], [%1], 16;\n"
                 :: "r"(dst), "l"(src));
}
__device__ __forceinline__ void cpa16z(uint32_t dst, const void* src, bool ok) {
    int sz = ok ? 16 : 0;
    asm volatile("cp.async.cg.shared.global [%0], [%1], 16, %2;\n"
                 :: "r"(dst), "l"(src), "r"(sz));
}

// issue one k-tile stage: A (contiguous permuted 8KB) + B (32k x 128n fp16)
__device__ __forceinline__ void gemm_stage_h(const __half* __restrict__ A,
                                             const __half* __restrict__ B,
                                             int K, int m0, int n0, int k0,
                                             uint32_t sa, uint32_t sb, int tid)
{
    const __half* Atile = A + ((long)((m0 >> 7) * (K >> 5) + (k0 >> 5))) * 4096;
    #pragma unroll
    for (int r = 0; r < 2; r++) {
        int idx = tid + r * 256;              // 0..511
        cpa16(sa + idx * 16, Atile + idx * 8);
    }
    #pragma unroll
    for (int r = 0; r < 2; r++) {
        int idx = tid + r * 256;              // 0..511
        int row = idx >> 5, cc = idx & 31;    // kp row, 4-pixel chunk
        int n = n0 + cc * 4;
        cpa16z(sb + (row * BST2 + cc * 4) * 4,
               B + ((long)((k0 >> 1) + row)) * 2 * NPIX + 2 * n, n < NPIX);
    }
    asm volatile("cp.async.commit_group;\n" ::: "memory");
}

// pipelined fp16 GEMM core: C[128x128] at (m0,n0) of A[M,K] x B[K,NPIX]
__device__ __forceinline__ void gemm_core_h(
    const __half* __restrict__ A, const __half* __restrict__ B,
    int K, int m0, int n0, uint32_t* smA, uint32_t* smB, float4 acc[4][4])
{
    const int tid = threadIdx.x;
    const int lane = tid & 31, warp = tid >> 5;
    const int wm = warp >> 2, wn = warp & 3;
    const int gi = lane >> 2, li = lane & 3;

    #pragma unroll
    for (int i = 0; i < 4; i++)
        #pragma unroll
        for (int j = 0; j < 4; j++) acc[i][j] = make_float4(0.f, 0.f, 0.f, 0.f);

    uint32_t saB = (uint32_t)__cvta_generic_to_shared(smA);
    uint32_t sbB = (uint32_t)__cvta_generic_to_shared(smB);

    const int nk = K >> 5;
    gemm_stage_h(A, B, K, m0, n0, 0, saB, sbB, tid);
    gemm_stage_h(A, B, K, m0, n0, 32, saB + A_W2 * 4, sbB + B_W2 * 4, tid);

    for (int kt = 0; kt < nk; kt++) {
        if (kt + 1 < nk)
            asm volatile("cp.async.wait_group 1;\n" ::: "memory");
        else
            asm volatile("cp.async.wait_group 0;\n" ::: "memory");
        __syncthreads();

        const uint32_t* Bs = smB + (kt % NSTAGE) * B_W2;
        const uint4* A4 = (const uint4*)(smA + (kt % NSTAGE) * A_W2);

        #pragma unroll
        for (int ks = 0; ks < 2; ks++) {
            uint32_t bf[4][2];
            #pragma unroll
            for (int j = 0; j < 4; j++) {
                int n = wn * 32 + j * 8 + gi;
                bf[j][0] = Bs[(ks * 8 + li) * BST2 + n];
                bf[j][1] = Bs[(ks * 8 + li + 4) * BST2 + n];
            }
            #pragma unroll
            for (int i = 0; i < 4; i++) {
                uint4 t4 = A4[(ks * 8 + wm * 4 + i) * 32 + lane];
                #pragma unroll
                for (int j = 0; j < 4; j++)
                    mma_f16(acc[i][j], t4.x, t4.y, t4.z, t4.w,
                            bf[j][0], bf[j][1], acc[i][j]);
            }
        }

        if (kt + 2 < nk) {
            int s = (kt + 2) % NSTAGE;
            gemm_stage_h(A, B, K, m0, n0, (kt + 2) * 32,
                         saB + s * A_W2 * 4, sbB + s * B_W2 * 4, tid);
        }
    }
}

// ---------------------------------------------------------------------------
// Kernel 0: round weights to fp16, permuted into m16n8k16 A-fragment order.
// ---------------------------------------------------------------------------
__global__ void prep_w_kernel(const float* __restrict__ pwq,
                              const float* __restrict__ pwk,
                              const float* __restrict__ pwv,
                              const float* __restrict__ wo)
{
    int i = blockIdx.x * 256 + threadIdx.x;
    if (i >= 4 * 131072) return;
    int seg = i >> 17;
    int j = i & 131071;
    float v;
    if (seg == 0)      v = pwq[j];
    else if (seg == 1) v = pwk[j];
    else if (seg == 2) v = pwv[j];
    else               v = wo[j];
    int K = (seg < 3) ? DIMC : INNER;
    int m = j / K, k = j % K;
    int ntk = K >> 5;
    int ml = m & 127, kl = k & 31;
    int matom = ml >> 4, row = ml & 15;
    int gi = row & 7, hi = row >> 3;
    int ks = kl >> 4, kk = kl & 15;
    int li = (kk >> 1) & 3, khigh = (kk >> 3) & 1, hsel = kk & 1;
    int lane = gi * 4 + li;
    int reg = hi + 2 * khigh;
    long off = (long)seg * 131072
             + ((long)((m >> 7) * ntk + (k >> 5))) * 4096
             + (((ks * 8 + matom) * 32 + lane) * 4 + reg) * 2 + hsel;
    g_wh[off] = __float2half_rn(v);
}

// ---------------------------------------------------------------------------
// Kernel 1: depthwise 3x3 conv + BN, fp16 pair-interleaved output
// ---------------------------------------------------------------------------
__global__ __launch_bounds__(256) void dwbn_kernel(const float* __restrict__ x,
    const float* __restrict__ qdw, const float* __restrict__ qg,
    const float* __restrict__ qb,  const float* __restrict__ qm,
    const float* __restrict__ qv,
    const float* __restrict__ kdw, const float* __restrict__ kg,
    const float* __restrict__ kb,  const float* __restrict__ km,
    const float* __restrict__ kv,
    const float* __restrict__ vdw, const float* __restrict__ vg,
    const float* __restrict__ vb,  const float* __restrict__ vm,
    const float* __restrict__ vv)
{
    const int NSTRIP = NPIX / 4;   // 784
    int idx = blockIdx.x * blockDim.x + threadIdx.x;
    if (idx >= BATCH * DIMC * NSTRIP) return;
    int s = idx % NSTRIP;
    int c = (idx / NSTRIP) % DIMC;
    int b = idx / (NSTRIP * DIMC);
    int p0 = s * 4;
    int yy = p0 / HW, xx0 = p0 % HW;

    float wq[9], wk[9], wv[9];
    #pragma unroll
    for (int t = 0; t < 9; t++) {
        wq[t] = __ldg(&qdw[c * 9 + t]);
        wk[t] = __ldg(&kdw[c * 9 + t]);
        wv[t] = __ldg(&vdw[c * 9 + t]);
    }

    const float* xb = x + ((long)(b * DIMC + c)) * NPIX;
    float aq[4] = {0.f, 0.f, 0.f, 0.f};
    float ak[4] = {0.f, 0.f, 0.f, 0.f};
    float av[4] = {0.f, 0.f, 0.f, 0.f};

    #pragma unroll
    for (int ky = 0; ky < 3; ky++) {
        int iy = yy + ky - 1;
        if (iy < 0 || iy >= HW) continue;
        const float* row = xb + iy * HW;
        float v[6];
        v[0] = (xx0 > 0) ? row[xx0 - 1] : 0.f;
        float4 mid = *(const float4*)&row[xx0];
        v[1] = mid.x; v[2] = mid.y; v[3] = mid.z; v[4] = mid.w;
        v[5] = (xx0 + 4 < HW) ? row[xx0 + 4] : 0.f;
        #pragma unroll
        for (int px = 0; px < 4; px++) {
            #pragma unroll
            for (int kx = 0; kx < 3; kx++) {
                float xv = v[px + kx];
                aq[px] += xv * wq[ky * 3 + kx];
                ak[px] += xv * wk[ky * 3 + kx];
                av[px] += xv * wv[ky * 3 + kx];
            }
        }
    }
    float sq = __ldg(&qg[c]) * rsqrtf(__ldg(&qv[c]) + 1e-5f);
    float sk = __ldg(&kg[c]) * rsqrtf(__ldg(&kv[c]) + 1e-5f);
    float sv = __ldg(&vg[c]) * rsqrtf(__ldg(&vv[c]) + 1e-5f);
    float mq = __ldg(&qm[c]), bq = __ldg(&qb[c]);
    float mk = __ldg(&km[c]), bk = __ldg(&kb[c]);
    float mv = __ldg(&vm[c]), bv = __ldg(&vb[c]);

    const long PLANE = (long)BATCH * DIMC * NPIX;
    long off = (long)b * DIMC * NPIX + (c >> 1) * 2L * NPIX + (c & 1) + 2L * p0;
    #pragma unroll
    for (int px = 0; px < 4; px++) {
        g_yh[off + 2 * px]             = __float2half_rn((aq[px] - mq) * sq + bq);
        g_yh[PLANE + off + 2 * px]     = __float2half_rn((ak[px] - mk) * sk + bk);
        g_yh[2 * PLANE + off + 2 * px] = __float2half_rn((av[px] - mv) * sv + bv);
    }
}

// ---------------------------------------------------------------------------
// Kernel 2: qkv GEMM (fp16). Q/K -> windowed [t*64+d]; V -> transposed [d][56]
// grid: (25, 4, 48)
// ---------------------------------------------------------------------------
__global__ __launch_bounds__(256) void gemm_qkv_kernel()
{
    extern __shared__ __align__(16) uint32_t smemw[];
    uint32_t* smA = smemw;
    uint32_t* smB = smemw + NSTAGE * A_W2;

    int z = blockIdx.z;
    int proj = z >> 4;
    int b = z & 15;
    const __half* A = g_wh + (long)proj * 131072;
    const __half* B = g_yh + ((long)proj * BATCH + b) * DIMC * NPIX;

    int m0 = blockIdx.y * 128;
    int n0 = blockIdx.x * 128;

    float4 acc[4][4];
    gemm_core_h(A, B, DIMC, m0, n0, smA, smB, acc);

    const int lane = threadIdx.x & 31, warp = threadIdx.x >> 5;
    const int wm = warp >> 2, wn = warp & 3;
    const int gid = lane >> 2, tig = lane & 3;

    if (proj < 2) {
        __half* dst = g_qkvh + (long)proj * BATCH * INNER * NPIX
                    + (long)b * HEADS * NWIN * NPIX;
        #pragma unroll
        for (int i = 0; i < 4; i++) {
            int o_lo = m0 + wm * 64 + i * 16 + gid;
            int o_hi = o_lo + 8;
            #pragma unroll
            for (int j = 0; j < 4; j++) {
                int p0 = n0 + wn * 32 + j * 8 + tig * 2;
                int p1 = p0 + 1;
                float vals[4] = {acc[i][j].x, acc[i][j].y, acc[i][j].z, acc[i][j].w};
                int os[4] = {o_lo, o_lo, o_hi, o_hi};
                int ps[4] = {p0, p1, p0, p1};
                #pragma unroll
                for (int e = 0; e < 4; e++) {
                    int p = ps[e];
                    if (p < NPIX) {
                        int o = os[e];
                        int h = o >> 6, dd = o & 63;
                        int yy = p / HW, xx = p % HW;
                        int w = (yy / WS) * 8 + (xx / WS);
                        int t = (yy % WS) * WS + (xx % WS);
                        dst[((long)(h * NWIN + w)) * NPIX + t * 64 + dd] =
                            __float2half_rn(vals[e]);
                    }
                }
            }
        }
    } else {
        __half* dstv = g_vT + (long)b * HEADS * NWIN * DHEAD * 56;
        #pragma unroll
        for (int i = 0; i < 4; i++) {
            int o_lo = m0 + wm * 64 + i * 16 + gid;
            int o_hi = o_lo + 8;
            #pragma unroll
            for (int j = 0; j < 4; j++) {
                int p0 = n0 + wn * 32 + j * 8 + tig * 2;
                int p1 = p0 + 1;
                float vals[4] = {acc[i][j].x, acc[i][j].y, acc[i][j].z, acc[i][j].w};
                int os[4] = {o_lo, o_lo, o_hi, o_hi};
                int ps[4] = {p0, p1, p0, p1};
                #pragma unroll
                for (int e = 0; e < 4; e++) {
                    int p = ps[e];
                    if (p < NPIX) {
                        int o = os[e];
                        int h = o >> 6, dd = o & 63;
                        int yy = p / HW, xx = p % HW;
                        int w = (yy / WS) * 8 + (xx / WS);
                        int t = (yy % WS) * WS + (xx % WS);
                        dstv[((long)(h * NWIN + w) * DHEAD + dd) * 56 + t] =
                            __float2half_rn(vals[e]);
                    }
                }
            }
        }
    }
}

// ---------------------------------------------------------------------------
// Kernel 3: windowed attention, fp16 m16n8k16.  grid: (NWIN, HEADS, BATCH)
// ---------------------------------------------------------------------------
__global__ __launch_bounds__(128) void attn_kernel(const float* __restrict__ pos_emb)
{
    __shared__ __align__(16) uint32_t Qs[64 * QST2];   // half2 words; aliased as Ps
    __shared__ __align__(16) uint32_t Ks[56 * KST2];
    __shared__ __align__(16) uint32_t Vs[64 * VST2];
    __shared__ float p48s[64];
    uint32_t* Ps = Qs;

    int w = blockIdx.x, h = blockIdx.y, b = blockIdx.z;
    int tid = threadIdx.x;
    int lane = tid & 31, warp = tid >> 5;
    int gi = lane >> 2, li = lane & 3;

    const long QK_PSTR = (long)BATCH * INNER * NPIX;
    long qbase = (((long)b * HEADS + h) * NWIN + w) * NPIX;
    const __half* gq = g_qkvh + qbase;
    const __half* gk = g_qkvh + QK_PSTR + qbase;
    const __half* gv = g_vT + (((long)b * HEADS + h) * NWIN + w) * (DHEAD * 56);

    uint32_t sQ = (uint32_t)__cvta_generic_to_shared(Qs);
    uint32_t sK = (uint32_t)__cvta_generic_to_shared(Ks);
    uint32_t sV = (uint32_t)__cvta_generic_to_shared(Vs);

    // zero K pad rows 49..55
    for (int i = tid; i < 7 * KST2; i += 128) {
        int t = NTOK + i / KST2, d = i % KST2;
        Ks[t * KST2 + d] = 0;
    }
    // group 0: Q + K  (49 rows x 8 chunks each)
    for (int i = tid; i < NTOK * 8; i += 128) {
        int t = i >> 3, c = i & 7;
        cpa16(sQ + (t * QST2) * 4 + c * 16, gq + t * 64 + c * 8);
        cpa16(sK + (t * KST2) * 4 + c * 16, gk + t * 64 + c * 8);
    }
    asm volatile("cp.async.commit_group;\n" ::: "memory");
    // group 1: V  (64 d-rows x 7 chunks)
    for (int i = tid; i < 64 * 7; i += 128) {
        int d = i / 7, c = i % 7;
        cpa16(sV + (d * VST2) * 4 + c * 16, gv + d * 56 + c * 8);
    }
    asm volatile("cp.async.commit_group;\n" ::: "memory");

    asm volatile("cp.async.wait_group 1;\n" ::: "memory");
    __syncthreads();

    int row_lo = warp * 16 + gi;
    int row_hi = row_lo + 8;

    // ---- phase 1: S = Q K^T  (M=64, N=56, K=64 in 4 ksteps of 16) ----
    uint32_t a[4][4];
    #pragma unroll
    for (int ks = 0; ks < 4; ks++) {
        a[ks][0] = Qs[row_lo * QST2 + ks * 8 + li];
        a[ks][1] = Qs[row_hi * QST2 + ks * 8 + li];
        a[ks][2] = Qs[row_lo * QST2 + ks * 8 + li + 4];
        a[ks][3] = Qs[row_hi * QST2 + ks * 8 + li + 4];
    }
    float4 c[7];
    #pragma unroll
    for (int j = 0; j < 7; j++) {
        c[j] = make_float4(0.f, 0.f, 0.f, 0.f);
        #pragma unroll
        for (int ks = 0; ks < 4; ks++) {
            uint32_t b0 = Ks[(j * 8 + gi) * KST2 + ks * 8 + li];
            uint32_t b1 = Ks[(j * 8 + gi) * KST2 + ks * 8 + li + 4];
            mma_f16(c[j], a[ks][0], a[ks][1], a[ks][2], a[ks][3], b0, b1, c[j]);
        }
    }

    // ---- bias + softmax in registers ----
    int rr_lo = row_lo / 7, rc_lo = row_lo % 7;
    int rr_hi = row_hi / 7, rc_hi = row_hi % 7;
    float vlo[14], vhi[14];
    #pragma unroll
    for (int j = 0; j < 7; j++) {
        #pragma unroll
        for (int e = 0; e < 2; e++) {
            int col = j * 8 + li * 2 + e;
            float s_lo = (e == 0) ? c[j].x : c[j].y;
            float s_hi = (e == 0) ? c[j].z : c[j].w;
            if (col < NTOK) {
                int cr = col / 7, cc = col % 7;
                int rel_lo = (cr - rr_lo + 6) * 13 + (cc - rc_lo + 6);
                int rel_hi = (cr - rr_hi + 6) * 13 + (cc - rc_hi + 6);
                rel_lo = min(max(rel_lo, 0), 168);
                rel_hi = min(max(rel_hi, 0), 168);
                vlo[j * 2 + e] = fmaf(s_lo, 0.125f, __ldg(&pos_emb[rel_lo * HEADS + h]));
                vhi[j * 2 + e] = fmaf(s_hi, 0.125f, __ldg(&pos_emb[rel_hi * HEADS + h]));
            } else {
                vlo[j * 2 + e] = -1e30f;
                vhi[j * 2 + e] = -1e30f;
            }
        }
    }
    float mlo = -1e30f, mhi = -1e30f;
    #pragma unroll
    for (int i = 0; i < 14; i++) { mlo = fmaxf(mlo, vlo[i]); mhi = fmaxf(mhi, vhi[i]); }
    mlo = fmaxf(mlo, __shfl_xor_sync(0xffffffffu, mlo, 1));
    mlo = fmaxf(mlo, __shfl_xor_sync(0xffffffffu, mlo, 2));
    mhi = fmaxf(mhi, __shfl_xor_sync(0xffffffffu, mhi, 1));
    mhi = fmaxf(mhi, __shfl_xor_sync(0xffffffffu, mhi, 2));
    float slo = 0.f, shi = 0.f;
    #pragma unroll
    for (int i = 0; i < 14; i++) {
        vlo[i] = __expf(vlo[i] - mlo); slo += vlo[i];
        vhi[i] = __expf(vhi[i] - mhi); shi += vhi[i];
    }
    slo += __shfl_xor_sync(0xffffffffu, slo, 1);
    slo += __shfl_xor_sync(0xffffffffu, slo, 2);
    shi += __shfl_xor_sync(0xffffffffu, shi, 1);
    shi += __shfl_xor_sync(0xffffffffu, shi, 2);
    float ilo = 1.f / slo, ihi = 1.f / shi;

    // V must be resident; all Qs reads done before overwrite as Ps
    asm volatile("cp.async.wait_group 0;\n" ::: "memory");
    __syncthreads();

    // store P as fp16 pairs (cols 0..47); col 48 goes to p48s (fp32)
    #pragma unroll
    for (int j = 0; j < 6; j++) {
        __half2 hlo = __halves2half2(__float2half_rn(vlo[j * 2] * ilo),
                                     __float2half_rn(vlo[j * 2 + 1] * ilo));
        __half2 hhi = __halves2half2(__float2half_rn(vhi[j * 2] * ihi),
                                     __float2half_rn(vhi[j * 2 + 1] * ihi));
        Ps[row_lo * QST2 + j * 4 + li] = *(uint32_t*)&hlo;
        Ps[row_hi * QST2 + j * 4 + li] = *(uint32_t*)&hhi;
    }
    if (li == 0) {
        p48s[row_lo] = vlo[12] * ilo;
        p48s[row_hi] = vhi[12] * ihi;
    }
    __syncthreads();

    // ---- phase 2: O = P V  (K=48 in 3 ksteps + rank-1 fixup for t=48) ----
    uint32_t pa[3][4];
    #pragma unroll
    for (int ks = 0; ks < 3; ks++) {
        pa[ks][0] = Ps[row_lo * QST2 + ks * 8 + li];
        pa[ks][1] = Ps[row_hi * QST2 + ks * 8 + li];
        pa[ks][2] = Ps[row_lo * QST2 + ks * 8 + li + 4];
        pa[ks][3] = Ps[row_hi * QST2 + ks * 8 + li + 4];
    }
    float pl48 = p48s[row_lo], ph48 = p48s[row_hi];

    uint32_t* gaw = (uint32_t*)g_ah;
    long wbase = (long)b * (INNER / 2) * NPIX + (long)w * NTOK;
    #pragma unroll
    for (int dn = 0; dn < 8; dn++) {
        float4 o = make_float4(0.f, 0.f, 0.f, 0.f);
        #pragma unroll
        for (int ks = 0; ks < 3; ks++) {
            uint32_t b0 = Vs[(dn * 8 + gi) * VST2 + ks * 8 + li];
            uint32_t b1 = Vs[(dn * 8 + gi) * VST2 + ks * 8 + li + 4];
            mma_f16(o, pa[ks][0], pa[ks][1], pa[ks][2], pa[ks][3], b0, b1, o);
        }
        int d0 = dn * 8 + 2 * li;
        float v48a = __half2float(__low2half(*(const __half2*)&Vs[d0 * VST2 + 24]));
        float v48b = __half2float(__low2half(*(const __half2*)&Vs[(d0 + 1) * VST2 + 24]));
        o.x += pl48 * v48a;  o.y += pl48 * v48b;
        o.z += ph48 * v48a;  o.w += ph48 * v48b;

        long cw = ((long)(h * 64 + d0) >> 1) * NPIX;
        if (row_lo < NTOK) {
            __half2 hv = __halves2half2(__float2half_rn(o.x), __float2half_rn(o.y));
            gaw[wbase + cw + row_lo] = *(uint32_t*)&hv;
        }
        if (row_hi < NTOK) {
            __half2 hv = __halves2half2(__float2half_rn(o.z), __float2half_rn(o.w));
            gaw[wbase + cw + row_hi] = *(uint32_t*)&hv;
        }
    }
}

// ---------------------------------------------------------------------------
// Kernel 4: out-projection GEMM (fp16) + bias, un-window on store
// grid: (25, 2, 16)
// ---------------------------------------------------------------------------
__global__ __launch_bounds__(256) void gemm_out_kernel(
    const float* __restrict__ ob, float* __restrict__ out)
{
    extern __shared__ __align__(16) uint32_t smemw[];
    uint32_t* smA = smemw;
    uint32_t* smB = smemw + NSTAGE * A_W2;

    int b = blockIdx.z;
    const __half* A = g_wh + 3L * 131072;
    const __half* B = g_ah + (long)b * INNER * NPIX;

    int m0 = blockIdx.y * 128;
    int n0 = blockIdx.x * 128;

    float4 acc[4][4];
    gemm_core_h(A, B, INNER, m0, n0, smA, smB, acc);

    const int lane = threadIdx.x & 31, warp = threadIdx.x >> 5;
    const int wm = warp >> 2, wn = warp & 3;
    const int gid = lane >> 2, tig = lane & 3;

    #pragma unroll
    for (int i = 0; i < 4; i++) {
        int o_lo = m0 + wm * 64 + i * 16 + gid;
        int o_hi = o_lo + 8;
        float bias_lo = __ldg(&ob[o_lo]);
        float bias_hi = __ldg(&ob[o_hi]);
        #pragma unroll
        for (int j = 0; j < 4; j++) {
            int p0 = n0 + wn * 32 + j * 8 + tig * 2;
            int p1 = p0 + 1;
            float vals[4] = {acc[i][j].x + bias_lo, acc[i][j].y + bias_lo,
                             acc[i][j].z + bias_hi, acc[i][j].w + bias_hi};
            int os[4] = {o_lo, o_lo, o_hi, o_hi};
            int ps[4] = {p0, p1, p0, p1};
            #pragma unroll
            for (int e = 0; e < 4; e++) {
                int p = ps[e];
                if (p < NPIX) {
                    int o = os[e];
                    int w = p / NTOK, t = p % NTOK;
                    int yy = (w / 8) * WS + t / WS;
                    int xx = (w % 8) * WS + t % WS;
                    out[((long)b * DIMC + o) * NPIX + yy * HW + xx] = vals[e];
                }
            }
        }
    }
}

// ---------------------------------------------------------------------------
extern "C" void kernel_launch(void* const* d_in, const int* in_sizes, int n_in,
                              void* d_out, int out_size)
{
    const float* x    = (const float*)d_in[0];
    const float* qdw  = (const float*)d_in[1];
    const float* qg   = (const float*)d_in[2];
    const float* qb   = (const float*)d_in[3];
    const float* qm   = (const float*)d_in[4];
    const float* qv   = (const float*)d_in[5];
    const float* qpw  = (const float*)d_in[6];
    const float* kdw  = (const float*)d_in[7];
    const float* kg   = (const float*)d_in[8];
    const float* kb   = (const float*)d_in[9];
    const float* km   = (const float*)d_in[10];
    const float* kv   = (const float*)d_in[11];
    const float* kpw  = (const float*)d_in[12];
    const float* vdw  = (const float*)d_in[13];
    const float* vg   = (const float*)d_in[14];
    const float* vb   = (const float*)d_in[15];
    const float* vm   = (const float*)d_in[16];
    const float* vv   = (const float*)d_in[17];
    const float* vpw  = (const float*)d_in[18];
    const float* pos  = (const float*)d_in[19];
    const float* outw = (const float*)d_in[20];
    const float* outb = (const float*)d_in[21];
    float* out = (float*)d_out;

    static bool attr_done = false;
    if (!attr_done) {
        cudaFuncSetAttribute(gemm_qkv_kernel,
            cudaFuncAttributeMaxDynamicSharedMemorySize, GEMM_SMEM_BYTES);
        cudaFuncSetAttribute(gemm_out_kernel,
            cudaFuncAttributeMaxDynamicSharedMemorySize, GEMM_SMEM_BYTES);
        attr_done = true;
    }

    prep_w_kernel<<<2048, 256>>>(qpw, kpw, vpw, outw);

    int nstrips = BATCH * DIMC * (NPIX / 4);
    dwbn_kernel<<<(nstrips + 255) / 256, 256>>>(x,
        qdw, qg, qb, qm, qv,
        kdw, kg, kb, km, kv,
        vdw, vg, vb, vm, vv);

    gemm_qkv_kernel<<<dim3(25, 4, 48), 256, GEMM_SMEM_BYTES>>>();

    attn_kernel<<<dim3(NWIN, HEADS, BATCH), 128>>>(pos);

    gemm_out_kernel<<<dim3(25, 2, 16), 256, GEMM_SMEM_BYTES>>>(outb, out);
}

// round 16
// speedup vs baseline: 1.7701x; 1.2199x over previous
#include <cuda_runtime.h>
#include <cuda_fp16.h>
#include <cstdint>

#define DIMC   256
#define INNER  512
#define HEADS  8
#define DHEAD  64
#define WS     7
#define NTOK   49
#define HW     56
#define NPIX   3136      // 56*56
#define BATCH  16
#define NWIN   64        // 8*8 windows

// ---- fp16 GEMM smem geometry (in 4-byte words = half2 units) ----
#define BST2   136                 // B tile row stride (128 data + 8 pad)
#define A_W2   2048                // A tile: 128m x 32k fp16 = 8KB
#define B_W2   (16 * BST2)         // 2176 words
#define NSTAGE 3
#define GEMM_SMEM_BYTES ((NSTAGE * (A_W2 + B_W2)) * 4)   // 50688

// ---- attn smem strides ----
#define QST2 36        // Q/K row stride in words (72 halves)
#define VSTW 36        // V row stride in words (72 halves)

// ---------------- scratch (device globals) ----------------
// dw+bn out, fp16, channel-pair interleaved: [proj][b][c>>1][p][2]
__device__ __align__(128) __half g_yh[3L * BATCH * DIMC * NPIX];
// Q,K,V fp16 windowed: [proj(3)][b][h][w][t*64+d]
__device__ __align__(128) __half g_qkvh[3L * BATCH * INNER * NPIX];
// attn out fp16, pair interleaved: [b][c>>1][p][2]
__device__ __align__(128) __half g_ah[(long)BATCH * INNER * NPIX];
// weights fp16, MMA-fragment permuted
__device__ __align__(128) __half g_wh[4L * 131072];

// ---------------------------------------------------------------------------
__device__ __forceinline__ void mma_f16(float4& d,
    uint32_t a0, uint32_t a1, uint32_t a2, uint32_t a3,
    uint32_t b0, uint32_t b1, const float4& c)
{
    asm volatile(
        "mma.sync.aligned.m16n8k16.row.col.f32.f16.f16.f32 "
        "{%0,%1,%2,%3}, {%4,%5,%6,%7}, {%8,%9}, {%10,%11,%12,%13};\n"
        : "=f"(d.x), "=f"(d.y), "=f"(d.z), "=f"(d.w)
        : "r"(a0), "r"(a1), "r"(a2), "r"(a3), "r"(b0), "r"(b1),
          "f"(c.x), "f"(c.y), "f"(c.z), "f"(c.w));
}

__device__ __forceinline__ void cpa16(uint32_t dst, const void* src) {
    asm volatile("cp.async.cg.shared.global [%0], [%1], 16;\n"
                 :: "r"(dst), "l"(src));
}
__device__ __forceinline__ void cpa16z(uint32_t dst, const void* src, bool ok) {
    int sz = ok ? 16 : 0;
    asm volatile("cp.async.cg.shared.global [%0], [%1], 16, %2;\n"
                 :: "r"(dst), "l"(src), "r"(sz));
}

// issue one k-tile stage: A (contiguous permuted 8KB) + B (32k x 128n fp16)
__device__ __forceinline__ void gemm_stage_h(const __half* __restrict__ A,
                                             const __half* __restrict__ B,
                                             int K, int m0, int n0, int k0,
                                             uint32_t sa, uint32_t sb, int tid)
{
    const __half* Atile = A + ((long)((m0 >> 7) * (K >> 5) + (k0 >> 5))) * 4096;
    #pragma unroll
    for (int r = 0; r < 2; r++) {
        int idx = tid + r * 256;
        cpa16(sa + idx * 16, Atile + idx * 8);
    }
    #pragma unroll
    for (int r = 0; r < 2; r++) {
        int idx = tid + r * 256;
        int row = idx >> 5, cc = idx & 31;
        int n = n0 + cc * 4;
        cpa16z(sb + (row * BST2 + cc * 4) * 4,
               B + ((long)((k0 >> 1) + row)) * 2 * NPIX + 2 * n, n < NPIX);
    }
    asm volatile("cp.async.commit_group;\n" ::: "memory");
}

// pipelined fp16 GEMM core: C[128x128] at (m0,n0) of A[M,K] x B[K,NPIX]
__device__ __forceinline__ void gemm_core_h(
    const __half* __restrict__ A, const __half* __restrict__ B,
    int K, int m0, int n0, uint32_t* smA, uint32_t* smB, float4 acc[4][4])
{
    const int tid = threadIdx.x;
    const int lane = tid & 31, warp = tid >> 5;
    const int wm = warp >> 2, wn = warp & 3;
    const int gi = lane >> 2, li = lane & 3;

    #pragma unroll
    for (int i = 0; i < 4; i++)
        #pragma unroll
        for (int j = 0; j < 4; j++) acc[i][j] = make_float4(0.f, 0.f, 0.f, 0.f);

    uint32_t saB = (uint32_t)__cvta_generic_to_shared(smA);
    uint32_t sbB = (uint32_t)__cvta_generic_to_shared(smB);

    const int nk = K >> 5;
    gemm_stage_h(A, B, K, m0, n0, 0, saB, sbB, tid);
    gemm_stage_h(A, B, K, m0, n0, 32, saB + A_W2 * 4, sbB + B_W2 * 4, tid);

    for (int kt = 0; kt < nk; kt++) {
        if (kt + 1 < nk)
            asm volatile("cp.async.wait_group 1;\n" ::: "memory");
        else
            asm volatile("cp.async.wait_group 0;\n" ::: "memory");
        __syncthreads();

        const uint32_t* Bs = smB + (kt % NSTAGE) * B_W2;
        const uint4* A4 = (const uint4*)(smA + (kt % NSTAGE) * A_W2);

        #pragma unroll
        for (int ks = 0; ks < 2; ks++) {
            uint32_t bf[4][2];
            #pragma unroll
            for (int j = 0; j < 4; j++) {
                int n = wn * 32 + j * 8 + gi;
                bf[j][0] = Bs[(ks * 8 + li) * BST2 + n];
                bf[j][1] = Bs[(ks * 8 + li + 4) * BST2 + n];
            }
            #pragma unroll
            for (int i = 0; i < 4; i++) {
                uint4 t4 = A4[(ks * 8 + wm * 4 + i) * 32 + lane];
                #pragma unroll
                for (int j = 0; j < 4; j++)
                    mma_f16(acc[i][j], t4.x, t4.y, t4.z, t4.w,
                            bf[j][0], bf[j][1], acc[i][j]);
            }
        }

        if (kt + 2 < nk) {
            int s = (kt + 2) % NSTAGE;
            gemm_stage_h(A, B, K, m0, n0, (kt + 2) * 32,
                         saB + s * A_W2 * 4, sbB + s * B_W2 * 4, tid);
        }
    }
}

// ---------------------------------------------------------------------------
// Kernel 0: round weights to fp16, permuted into m16n8k16 A-fragment order.
// ---------------------------------------------------------------------------
__global__ void prep_w_kernel(const float* __restrict__ pwq,
                              const float* __restrict__ pwk,
                              const float* __restrict__ pwv,
                              const float* __restrict__ wo)
{
    int i = blockIdx.x * 256 + threadIdx.x;
    if (i >= 4 * 131072) return;
    int seg = i >> 17;
    int j = i & 131071;
    float v;
    if (seg == 0)      v = pwq[j];
    else if (seg == 1) v = pwk[j];
    else if (seg == 2) v = pwv[j];
    else               v = wo[j];
    int K = (seg < 3) ? DIMC : INNER;
    int m = j / K, k = j % K;
    int ntk = K >> 5;
    int ml = m & 127, kl = k & 31;
    int matom = ml >> 4, row = ml & 15;
    int gi = row & 7, hi = row >> 3;
    int ks = kl >> 4, kk = kl & 15;
    int li = (kk >> 1) & 3, khigh = (kk >> 3) & 1, hsel = kk & 1;
    int lane = gi * 4 + li;
    int reg = hi + 2 * khigh;
    long off = (long)seg * 131072
             + ((long)((m >> 7) * ntk + (k >> 5))) * 4096
             + (((ks * 8 + matom) * 32 + lane) * 4 + reg) * 2 + hsel;
    g_wh[off] = __float2half_rn(v);
}

// ---------------------------------------------------------------------------
// Kernel 1: depthwise 3x3 conv + BN; one thread = channel-pair x 4 pixels.
// Stores one uint4 (8 halves, pair-interleaved) per projection: coalesced.
// ---------------------------------------------------------------------------
__global__ __launch_bounds__(256) void dwbn_kernel(const float* __restrict__ x,
    const float* __restrict__ qdw, const float* __restrict__ qg,
    const float* __restrict__ qb,  const float* __restrict__ qm,
    const float* __restrict__ qv,
    const float* __restrict__ kdw, const float* __restrict__ kg,
    const float* __restrict__ kb,  const float* __restrict__ km,
    const float* __restrict__ kv,
    const float* __restrict__ vdw, const float* __restrict__ vg,
    const float* __restrict__ vb,  const float* __restrict__ vm,
    const float* __restrict__ vv)
{
    const int NSTRIP = NPIX / 4;   // 784
    const int C2 = DIMC / 2;       // 128
    int idx = blockIdx.x * blockDim.x + threadIdx.x;
    if (idx >= BATCH * C2 * NSTRIP) return;
    int s = idx % NSTRIP;
    int c2 = (idx / NSTRIP) % C2;
    int b = idx / (NSTRIP * C2);
    int p0 = s * 4;
    int yy = p0 / HW, xx0 = p0 % HW;

    float oq[2][4], ok[2][4], ov[2][4];

    #pragma unroll
    for (int ch = 0; ch < 2; ch++) {
        int c = c2 * 2 + ch;
        float wq[9], wk[9], wv[9];
        #pragma unroll
        for (int t = 0; t < 9; t++) {
            wq[t] = __ldg(&qdw[c * 9 + t]);
            wk[t] = __ldg(&kdw[c * 9 + t]);
            wv[t] = __ldg(&vdw[c * 9 + t]);
        }
        const float* xb = x + ((long)(b * DIMC + c)) * NPIX;
        float aq[4] = {0.f, 0.f, 0.f, 0.f};
        float ak[4] = {0.f, 0.f, 0.f, 0.f};
        float av[4] = {0.f, 0.f, 0.f, 0.f};
        #pragma unroll
        for (int ky = 0; ky < 3; ky++) {
            int iy = yy + ky - 1;
            if (iy < 0 || iy >= HW) continue;
            const float* row = xb + iy * HW;
            float v[6];
            v[0] = (xx0 > 0) ? row[xx0 - 1] : 0.f;
            float4 mid = *(const float4*)&row[xx0];
            v[1] = mid.x; v[2] = mid.y; v[3] = mid.z; v[4] = mid.w;
            v[5] = (xx0 + 4 < HW) ? row[xx0 + 4] : 0.f;
            #pragma unroll
            for (int px = 0; px < 4; px++) {
                #pragma unroll
                for (int kx = 0; kx < 3; kx++) {
                    float xv = v[px + kx];
                    aq[px] += xv * wq[ky * 3 + kx];
                    ak[px] += xv * wk[ky * 3 + kx];
                    av[px] += xv * wv[ky * 3 + kx];
                }
            }
        }
        float sq = __ldg(&qg[c]) * rsqrtf(__ldg(&qv[c]) + 1e-5f);
        float sk = __ldg(&kg[c]) * rsqrtf(__ldg(&kv[c]) + 1e-5f);
        float sv = __ldg(&vg[c]) * rsqrtf(__ldg(&vv[c]) + 1e-5f);
        float mq = __ldg(&qm[c]), bq = __ldg(&qb[c]);
        float mk = __ldg(&km[c]), bk = __ldg(&kb[c]);
        float mv = __ldg(&vm[c]), bv = __ldg(&vb[c]);
        #pragma unroll
        for (int px = 0; px < 4; px++) {
            oq[ch][px] = (aq[px] - mq) * sq + bq;
            ok[ch][px] = (ak[px] - mk) * sk + bk;
            ov[ch][px] = (av[px] - mv) * sv + bv;
        }
    }

    const long PLANE_W = (long)BATCH * C2 * NPIX;       // words per plane
    long woff = ((long)(b * C2 + c2)) * NPIX + p0;      // word index
    uint32_t* gw = (uint32_t*)g_yh;
    uint4 pq, pk, pv;
    uint32_t* pqw = (uint32_t*)&pq;
    uint32_t* pkw = (uint32_t*)&pk;
    uint32_t* pvw = (uint32_t*)&pv;
    #pragma unroll
    for (int px = 0; px < 4; px++) {
        __half2 hq = __halves2half2(__float2half_rn(oq[0][px]), __float2half_rn(oq[1][px]));
        __half2 hk = __halves2half2(__float2half_rn(ok[0][px]), __float2half_rn(ok[1][px]));
        __half2 hv = __halves2half2(__float2half_rn(ov[0][px]), __float2half_rn(ov[1][px]));
        pqw[px] = *(uint32_t*)&hq;
        pkw[px] = *(uint32_t*)&hk;
        pvw[px] = *(uint32_t*)&hv;
    }
    *(uint4*)&gw[woff]               = pq;
    *(uint4*)&gw[PLANE_W + woff]     = pk;
    *(uint4*)&gw[2 * PLANE_W + woff] = pv;
}

// ---------------------------------------------------------------------------
// Kernel 2: qkv GEMM (fp16). Q/K/V all -> windowed [h][w][t*64+d]
// grid: (25, 4, 48)
// ---------------------------------------------------------------------------
__global__ __launch_bounds__(256) void gemm_qkv_kernel()
{
    extern __shared__ __align__(16) uint32_t smemw[];
    uint32_t* smA = smemw;
    uint32_t* smB = smemw + NSTAGE * A_W2;

    int z = blockIdx.z;
    int proj = z >> 4;
    int b = z & 15;
    const __half* A = g_wh + (long)proj * 131072;
    const __half* B = g_yh + ((long)proj * BATCH + b) * DIMC * NPIX;

    int m0 = blockIdx.y * 128;
    int n0 = blockIdx.x * 128;

    float4 acc[4][4];
    gemm_core_h(A, B, DIMC, m0, n0, smA, smB, acc);

    const int lane = threadIdx.x & 31, warp = threadIdx.x >> 5;
    const int wm = warp >> 2, wn = warp & 3;
    const int gid = lane >> 2, tig = lane & 3;

    __half* dst = g_qkvh + ((long)proj * BATCH + b) * HEADS * NWIN * NPIX;
    #pragma unroll
    for (int i = 0; i < 4; i++) {
        int o_lo = m0 + wm * 64 + i * 16 + gid;
        int o_hi = o_lo + 8;
        #pragma unroll
        for (int j = 0; j < 4; j++) {
            int p0 = n0 + wn * 32 + j * 8 + tig * 2;
            int p1 = p0 + 1;
            float vals[4] = {acc[i][j].x, acc[i][j].y, acc[i][j].z, acc[i][j].w};
            int os[4] = {o_lo, o_lo, o_hi, o_hi};
            int ps[4] = {p0, p1, p0, p1};
            #pragma unroll
            for (int e = 0; e < 4; e++) {
                int p = ps[e];
                if (p < NPIX) {
                    int o = os[e];
                    int h = o >> 6, dd = o & 63;
                    int yy = p / HW, xx = p % HW;
                    int w = (yy / WS) * 8 + (xx / WS);
                    int t = (yy % WS) * WS + (xx % WS);
                    dst[((long)(h * NWIN + w)) * NPIX + t * 64 + dd] =
                        __float2half_rn(vals[e]);
                }
            }
        }
    }
}

// ---------------------------------------------------------------------------
// Kernel 3: windowed attention, fp16; phase-2 B via ldmatrix.x4.trans.
// grid: (NWIN, HEADS, BATCH)
// ---------------------------------------------------------------------------
__global__ __launch_bounds__(128) void attn_kernel(const float* __restrict__ pos_emb)
{
    __shared__ __align__(16) uint32_t Qs[64 * QST2];   // aliased as Ps
    __shared__ __align__(16) uint32_t Ks[56 * QST2];
    __shared__ __align__(16) uint32_t Vs[50 * VSTW];   // rows 0..48 used
    __shared__ float p48s[64];
    uint32_t* Ps = Qs;

    int w = blockIdx.x, h = blockIdx.y, b = blockIdx.z;
    int tid = threadIdx.x;
    int lane = tid & 31, warp = tid >> 5;
    int gi = lane >> 2, li = lane & 3;

    const long PSTR = (long)BATCH * INNER * NPIX;
    long qbase = (((long)b * HEADS + h) * NWIN + w) * NPIX;
    const __half* gq = g_qkvh + qbase;
    const __half* gk = g_qkvh + PSTR + qbase;
    const __half* gv = g_qkvh + 2 * PSTR + qbase;

    uint32_t sQ = (uint32_t)__cvta_generic_to_shared(Qs);
    uint32_t sK = (uint32_t)__cvta_generic_to_shared(Ks);
    uint32_t sV = (uint32_t)__cvta_generic_to_shared(Vs);

    // zero K pad rows 49..55
    for (int i = tid; i < 7 * QST2; i += 128) {
        int t = NTOK + i / QST2, d = i % QST2;
        Ks[t * QST2 + d] = 0;
    }
    // group 0: Q + K
    for (int i = tid; i < NTOK * 8; i += 128) {
        int t = i >> 3, c = i & 7;
        cpa16(sQ + (t * QST2) * 4 + c * 16, gq + t * 64 + c * 8);
        cpa16(sK + (t * QST2) * 4 + c * 16, gk + t * 64 + c * 8);
    }
    asm volatile("cp.async.commit_group;\n" ::: "memory");
    // group 1: V rows [t][d]
    for (int i = tid; i < NTOK * 8; i += 128) {
        int t = i >> 3, c = i & 7;
        cpa16(sV + (t * VSTW) * 4 + c * 16, gv + t * 64 + c * 8);
    }
    asm volatile("cp.async.commit_group;\n" ::: "memory");

    asm volatile("cp.async.wait_group 1;\n" ::: "memory");
    __syncthreads();

    int row_lo = warp * 16 + gi;
    int row_hi = row_lo + 8;

    // ---- phase 1: S = Q K^T ----
    uint32_t a[4][4];
    #pragma unroll
    for (int ks = 0; ks < 4; ks++) {
        a[ks][0] = Qs[row_lo * QST2 + ks * 8 + li];
        a[ks][1] = Qs[row_hi * QST2 + ks * 8 + li];
        a[ks][2] = Qs[row_lo * QST2 + ks * 8 + li + 4];
        a[ks][3] = Qs[row_hi * QST2 + ks * 8 + li + 4];
    }
    float4 c[7];
    #pragma unroll
    for (int j = 0; j < 7; j++) {
        c[j] = make_float4(0.f, 0.f, 0.f, 0.f);
        #pragma unroll
        for (int ks = 0; ks < 4; ks++) {
            uint32_t b0 = Ks[(j * 8 + gi) * QST2 + ks * 8 + li];
            uint32_t b1 = Ks[(j * 8 + gi) * QST2 + ks * 8 + li + 4];
            mma_f16(c[j], a[ks][0], a[ks][1], a[ks][2], a[ks][3], b0, b1, c[j]);
        }
    }

    // ---- bias + softmax in registers ----
    int rr_lo = row_lo / 7, rc_lo = row_lo % 7;
    int rr_hi = row_hi / 7, rc_hi = row_hi % 7;
    float vlo[14], vhi[14];
    #pragma unroll
    for (int j = 0; j < 7; j++) {
        #pragma unroll
        for (int e = 0; e < 2; e++) {
            int col = j * 8 + li * 2 + e;
            float s_lo = (e == 0) ? c[j].x : c[j].y;
            float s_hi = (e == 0) ? c[j].z : c[j].w;
            if (col < NTOK) {
                int cr = col / 7, cc = col % 7;
                int rel_lo = (cr - rr_lo + 6) * 13 + (cc - rc_lo + 6);
                int rel_hi = (cr - rr_hi + 6) * 13 + (cc - rc_hi + 6);
                rel_lo = min(max(rel_lo, 0), 168);
                rel_hi = min(max(rel_hi, 0), 168);
                vlo[j * 2 + e] = fmaf(s_lo, 0.125f, __ldg(&pos_emb[rel_lo * HEADS + h]));
                vhi[j * 2 + e] = fmaf(s_hi, 0.125f, __ldg(&pos_emb[rel_hi * HEADS + h]));
            } else {
                vlo[j * 2 + e] = -1e30f;
                vhi[j * 2 + e] = -1e30f;
            }
        }
    }
    float mlo = -1e30f, mhi = -1e30f;
    #pragma unroll
    for (int i = 0; i < 14; i++) { mlo = fmaxf(mlo, vlo[i]); mhi = fmaxf(mhi, vhi[i]); }
    mlo = fmaxf(mlo, __shfl_xor_sync(0xffffffffu, mlo, 1));
    mlo = fmaxf(mlo, __shfl_xor_sync(0xffffffffu, mlo, 2));
    mhi = fmaxf(mhi, __shfl_xor_sync(0xffffffffu, mhi, 1));
    mhi = fmaxf(mhi, __shfl_xor_sync(0xffffffffu, mhi, 2));
    float slo = 0.f, shi = 0.f;
    #pragma unroll
    for (int i = 0; i < 14; i++) {
        vlo[i] = __expf(vlo[i] - mlo); slo += vlo[i];
        vhi[i] = __expf(vhi[i] - mhi); shi += vhi[i];
    }
    slo += __shfl_xor_sync(0xffffffffu, slo, 1);
    slo += __shfl_xor_sync(0xffffffffu, slo, 2);
    shi += __shfl_xor_sync(0xffffffffu, shi, 1);
    shi += __shfl_xor_sync(0xffffffffu, shi, 2);
    float ilo = 1.f / slo, ihi = 1.f / shi;

    asm volatile("cp.async.wait_group 0;\n" ::: "memory");
    __syncthreads();

    // store P as fp16 pairs (cols 0..47); col 48 -> p48s (fp32)
    #pragma unroll
    for (int j = 0; j < 6; j++) {
        __half2 hlo = __halves2half2(__float2half_rn(vlo[j * 2] * ilo),
                                     __float2half_rn(vlo[j * 2 + 1] * ilo));
        __half2 hhi = __halves2half2(__float2half_rn(vhi[j * 2] * ihi),
                                     __float2half_rn(vhi[j * 2 + 1] * ihi));
        Ps[row_lo * QST2 + j * 4 + li] = *(uint32_t*)&hlo;
        Ps[row_hi * QST2 + j * 4 + li] = *(uint32_t*)&hhi;
    }
    if (li == 0) {
        p48s[row_lo] = vlo[12] * ilo;
        p48s[row_hi] = vhi[12] * ihi;
    }
    __syncthreads();

    // ---- phase 2: O = P V  (K=48 via ldmatrix.trans; rank-1 fixup t=48) ----
    uint32_t pa[3][4];
    #pragma unroll
    for (int ks = 0; ks < 3; ks++) {
        pa[ks][0] = Ps[row_lo * QST2 + ks * 8 + li];
        pa[ks][1] = Ps[row_hi * QST2 + ks * 8 + li];
        pa[ks][2] = Ps[row_lo * QST2 + ks * 8 + li + 4];
        pa[ks][3] = Ps[row_hi * QST2 + ks * 8 + li + 4];
    }
    float pl48 = p48s[row_lo], ph48 = p48s[row_hi];
    const __half* Vh = (const __half*)Vs;

    uint32_t* gaw = (uint32_t*)g_ah;
    long wbase = (long)b * (INNER / 2) * NPIX + (long)w * NTOK;

    #pragma unroll
    for (int dblk = 0; dblk < 4; dblk++) {
        float4 oA = make_float4(0.f, 0.f, 0.f, 0.f);
        float4 oB = make_float4(0.f, 0.f, 0.f, 0.f);
        #pragma unroll
        for (int ks = 0; ks < 3; ks++) {
            int tRow = ks * 16 + (lane & 15);
            int dcol = dblk * 16 + ((lane >> 4) << 3);
            uint32_t addr = sV + (tRow * VSTW) * 4 + dcol * 2;
            uint32_t r0, r1, r2, r3;
            asm volatile(
                "ldmatrix.sync.aligned.m8n8.x4.trans.shared.b16 {%0,%1,%2,%3}, [%4];\n"
                : "=r"(r0), "=r"(r1), "=r"(r2), "=r"(r3) : "r"(addr));
            mma_f16(oA, pa[ks][0], pa[ks][1], pa[ks][2], pa[ks][3], r0, r1, oA);
            mma_f16(oB, pa[ks][0], pa[ks][1], pa[ks][2], pa[ks][3], r2, r3, oB);
        }
        #pragma unroll
        for (int half = 0; half < 2; half++) {
            float4 o = half ? oB : oA;
            int dn = dblk * 2 + half;
            int d0 = dn * 8 + 2 * li;
            float v48a = __half2float(Vh[48 * (VSTW * 2) + d0]);
            float v48b = __half2float(Vh[48 * (VSTW * 2) + d0 + 1]);
            o.x += pl48 * v48a;  o.y += pl48 * v48b;
            o.z += ph48 * v48a;  o.w += ph48 * v48b;

            long cw = ((long)(h * 64 + d0) >> 1) * NPIX;
            if (row_lo < NTOK) {
                __half2 hv = __halves2half2(__float2half_rn(o.x), __float2half_rn(o.y));
                gaw[wbase + cw + row_lo] = *(uint32_t*)&hv;
            }
            if (row_hi < NTOK) {
                __half2 hv = __halves2half2(__float2half_rn(o.z), __float2half_rn(o.w));
                gaw[wbase + cw + row_hi] = *(uint32_t*)&hv;
            }
        }
    }
}

// ---------------------------------------------------------------------------
// Kernel 4: out-projection GEMM (fp16) + bias, un-window on store
// grid: (25, 2, 16)
// ---------------------------------------------------------------------------
__global__ __launch_bounds__(256) void gemm_out_kernel(
    const float* __restrict__ ob, float* __restrict__ out)
{
    extern __shared__ __align__(16) uint32_t smemw[];
    uint32_t* smA = smemw;
    uint32_t* smB = smemw + NSTAGE * A_W2;

    int b = blockIdx.z;
    const __half* A = g_wh + 3L * 131072;
    const __half* B = g_ah + (long)b * INNER * NPIX;

    int m0 = blockIdx.y * 128;
    int n0 = blockIdx.x * 128;

    float4 acc[4][4];
    gemm_core_h(A, B, INNER, m0, n0, smA, smB, acc);

    const int lane = threadIdx.x & 31, warp = threadIdx.x >> 5;
    const int wm = warp >> 2, wn = warp & 3;
    const int gid = lane >> 2, tig = lane & 3;

    #pragma unroll
    for (int i = 0; i < 4; i++) {
        int o_lo = m0 + wm * 64 + i * 16 + gid;
        int o_hi = o_lo + 8;
        float bias_lo = __ldg(&ob[o_lo]);
        float bias_hi = __ldg(&ob[o_hi]);
        #pragma unroll
        for (int j = 0; j < 4; j++) {
            int p0 = n0 + wn * 32 + j * 8 + tig * 2;
            int p1 = p0 + 1;
            float vals[4] = {acc[i][j].x + bias_lo, acc[i][j].y + bias_lo,
                             acc[i][j].z + bias_hi, acc[i][j].w + bias_hi};
            int os[4] = {o_lo, o_lo, o_hi, o_hi};
            int ps[4] = {p0, p1, p0, p1};
            #pragma unroll
            for (int e = 0; e < 4; e++) {
                int p = ps[e];
                if (p < NPIX) {
                    int o = os[e];
                    int w = p / NTOK, t = p % NTOK;
                    int yy = (w / 8) * WS + t / WS;
                    int xx = (w % 8) * WS + t % WS;
                    out[((long)b * DIMC + o) * NPIX + yy * HW + xx] = vals[e];
                }
            }
        }
    }
}

// ---------------------------------------------------------------------------
extern "C" void kernel_launch(void* const* d_in, const int* in_sizes, int n_in,
                              void* d_out, int out_size)
{
    const float* x    = (const float*)d_in[0];
    const float* qdw  = (const float*)d_in[1];
    const float* qg   = (const float*)d_in[2];
    const float* qb   = (const float*)d_in[3];
    const float* qm   = (const float*)d_in[4];
    const float* qv   = (const float*)d_in[5];
    const float* qpw  = (const float*)d_in[6];
    const float* kdw  = (const float*)d_in[7];
    const float* kg   = (const float*)d_in[8];
    const float* kb   = (const float*)d_in[9];
    const float* km   = (const float*)d_in[10];
    const float* kv   = (const float*)d_in[11];
    const float* kpw  = (const float*)d_in[12];
    const float* vdw  = (const float*)d_in[13];
    const float* vg   = (const float*)d_in[14];
    const float* vb   = (const float*)d_in[15];
    const float* vm   = (const float*)d_in[16];
    const float* vv   = (const float*)d_in[17];
    const float* vpw  = (const float*)d_in[18];
    const float* pos  = (const float*)d_in[19];
    const float* outw = (const float*)d_in[20];
    const float* outb = (const float*)d_in[21];
    float* out = (float*)d_out;

    static bool attr_done = false;
    if (!attr_done) {
        cudaFuncSetAttribute(gemm_qkv_kernel,
            cudaFuncAttributeMaxDynamicSharedMemorySize, GEMM_SMEM_BYTES);
        cudaFuncSetAttribute(gemm_out_kernel,
            cudaFuncAttributeMaxDynamicSharedMemorySize, GEMM_SMEM_BYTES);
        attr_done = true;
    }

    prep_w_kernel<<<2048, 256>>>(qpw, kpw, vpw, outw);

    int npair = BATCH * (DIMC / 2) * (NPIX / 4);
    dwbn_kernel<<<(npair + 255) / 256, 256>>>(x,
        qdw, qg, qb, qm, qv,
        kdw, kg, kb, km, kv,
        vdw, vg, vb, vm, vv);

    gemm_qkv_kernel<<<dim3(25, 4, 48), 256, GEMM_SMEM_BYTES>>>();

    attn_kernel<<<dim3(NWIN, HEADS, BATCH), 128>>>(pos);

    gemm_out_kernel<<<dim3(25, 2, 16), 256, GEMM_SMEM_BYTES>>>(outb, out);
}

// round 17
// speedup vs baseline: 2.0498x; 1.1580x over previous
#include <cuda_runtime.h>
#include <cuda_fp16.h>
#include <cstdint>

#define DIMC   256
#define INNER  512
#define HEADS  8
#define DHEAD  64
#define WS     7
#define NTOK   49
#define HW     56
#define NPIX   3136      // 56*56
#define BATCH  16
#define NWIN   64        // 8*8 windows

// ---- fp16 GEMM smem geometry (in 4-byte words = half2 units) ----
#define BST2   136                 // B tile row stride (128 data + 8 pad)
#define A_W2   2048                // A tile: 128m x 32k fp16 = 8KB
#define B_W2   (16 * BST2)         // 2176 words
#define NSTAGE 3
#define GEMM_SMEM_BYTES ((NSTAGE * (A_W2 + B_W2)) * 4)   // 50688

// ---- attn smem strides ----
#define QST2 36        // Q/K row stride in words (72 halves)
#define VSTW 36        // V row stride in words (72 halves)

// ---------------- scratch (device globals) ----------------
// dw+bn out, fp16, channel-pair interleaved: [proj][b][c>>1][p][2]
__device__ __align__(128) __half g_yh[3L * BATCH * DIMC * NPIX];
// Q,K,V fp16 windowed: [proj(3)][b][h][w][t*64+d]
__device__ __align__(128) __half g_qkvh[3L * BATCH * INNER * NPIX];
// attn out fp16, pair interleaved: [b][c>>1][p][2]
__device__ __align__(128) __half g_ah[(long)BATCH * INNER * NPIX];
// weights fp16, MMA-fragment permuted
__device__ __align__(128) __half g_wh[4L * 131072];

// ---------------------------------------------------------------------------
__device__ __forceinline__ void mma_f16(float4& d,
    uint32_t a0, uint32_t a1, uint32_t a2, uint32_t a3,
    uint32_t b0, uint32_t b1, const float4& c)
{
    asm volatile(
        "mma.sync.aligned.m16n8k16.row.col.f32.f16.f16.f32 "
        "{%0,%1,%2,%3}, {%4,%5,%6,%7}, {%8,%9}, {%10,%11,%12,%13};\n"
        : "=f"(d.x), "=f"(d.y), "=f"(d.z), "=f"(d.w)
        : "r"(a0), "r"(a1), "r"(a2), "r"(a3), "r"(b0), "r"(b1),
          "f"(c.x), "f"(c.y), "f"(c.z), "f"(c.w));
}

__device__ __forceinline__ void cpa16(uint32_t dst, const void* src) {
    asm volatile("cp.async.cg.shared.global [%0], [%1], 16;\n"
                 :: "r"(dst), "l"(src));
}
__device__ __forceinline__ void cpa16z(uint32_t dst, const void* src, bool ok) {
    int sz = ok ? 16 : 0;
    asm volatile("cp.async.cg.shared.global [%0], [%1], 16, %2;\n"
                 :: "r"(dst), "l"(src), "r"(sz));
}

// issue one k-tile stage: A (contiguous permuted 8KB) + B (32k x 128n fp16)
__device__ __forceinline__ void gemm_stage_h(const __half* __restrict__ A,
                                             const __half* __restrict__ B,
                                             int K, int m0, int n0, int k0,
                                             uint32_t sa, uint32_t sb, int tid)
{
    const __half* Atile = A + ((long)((m0 >> 7) * (K >> 5) + (k0 >> 5))) * 4096;
    #pragma unroll
    for (int r = 0; r < 2; r++) {
        int idx = tid + r * 256;
        cpa16(sa + idx * 16, Atile + idx * 8);
    }
    #pragma unroll
    for (int r = 0; r < 2; r++) {
        int idx = tid + r * 256;
        int row = idx >> 5, cc = idx & 31;
        int n = n0 + cc * 4;
        cpa16z(sb + (row * BST2 + cc * 4) * 4,
               B + ((long)((k0 >> 1) + row)) * 2 * NPIX + 2 * n, n < NPIX);
    }
    asm volatile("cp.async.commit_group;\n" ::: "memory");
}

// pipelined fp16 GEMM core: C[128x128] at (m0,n0) of A[M,K] x B[K,NPIX]
__device__ __forceinline__ void gemm_core_h(
    const __half* __restrict__ A, const __half* __restrict__ B,
    int K, int m0, int n0, uint32_t* smA, uint32_t* smB, float4 acc[4][4])
{
    const int tid = threadIdx.x;
    const int lane = tid & 31, warp = tid >> 5;
    const int wm = warp >> 2, wn = warp & 3;
    const int gi = lane >> 2, li = lane & 3;

    #pragma unroll
    for (int i = 0; i < 4; i++)
        #pragma unroll
        for (int j = 0; j < 4; j++) acc[i][j] = make_float4(0.f, 0.f, 0.f, 0.f);

    uint32_t saB = (uint32_t)__cvta_generic_to_shared(smA);
    uint32_t sbB = (uint32_t)__cvta_generic_to_shared(smB);

    const int nk = K >> 5;
    gemm_stage_h(A, B, K, m0, n0, 0, saB, sbB, tid);
    gemm_stage_h(A, B, K, m0, n0, 32, saB + A_W2 * 4, sbB + B_W2 * 4, tid);

    for (int kt = 0; kt < nk; kt++) {
        if (kt + 1 < nk)
            asm volatile("cp.async.wait_group 1;\n" ::: "memory");
        else
            asm volatile("cp.async.wait_group 0;\n" ::: "memory");
        __syncthreads();

        const uint32_t* Bs = smB + (kt % NSTAGE) * B_W2;
        const uint4* A4 = (const uint4*)(smA + (kt % NSTAGE) * A_W2);

        #pragma unroll
        for (int ks = 0; ks < 2; ks++) {
            uint32_t bf[4][2];
            #pragma unroll
            for (int j = 0; j < 4; j++) {
                int n = wn * 32 + j * 8 + gi;
                bf[j][0] = Bs[(ks * 8 + li) * BST2 + n];
                bf[j][1] = Bs[(ks * 8 + li + 4) * BST2 + n];
            }
            #pragma unroll
            for (int i = 0; i < 4; i++) {
                uint4 t4 = A4[(ks * 8 + wm * 4 + i) * 32 + lane];
                #pragma unroll
                for (int j = 0; j < 4; j++)
                    mma_f16(acc[i][j], t4.x, t4.y, t4.z, t4.w,
                            bf[j][0], bf[j][1], acc[i][j]);
            }
        }

        if (kt + 2 < nk) {
            int s = (kt + 2) % NSTAGE;
            gemm_stage_h(A, B, K, m0, n0, (kt + 2) * 32,
                         saB + s * A_W2 * 4, sbB + s * B_W2 * 4, tid);
        }
    }
}

// ---------------------------------------------------------------------------
// Kernel 0: round weights to fp16, permuted into m16n8k16 A-fragment order.
// ---------------------------------------------------------------------------
__global__ void prep_w_kernel(const float* __restrict__ pwq,
                              const float* __restrict__ pwk,
                              const float* __restrict__ pwv,
                              const float* __restrict__ wo)
{
    int i = blockIdx.x * 256 + threadIdx.x;
    if (i >= 4 * 131072) return;
    int seg = i >> 17;
    int j = i & 131071;
    float v;
    if (seg == 0)      v = pwq[j];
    else if (seg == 1) v = pwk[j];
    else if (seg == 2) v = pwv[j];
    else               v = wo[j];
    int K = (seg < 3) ? DIMC : INNER;
    int m = j / K, k = j % K;
    int ntk = K >> 5;
    int ml = m & 127, kl = k & 31;
    int matom = ml >> 4, row = ml & 15;
    int gi = row & 7, hi = row >> 3;
    int ks = kl >> 4, kk = kl & 15;
    int li = (kk >> 1) & 3, khigh = (kk >> 3) & 1, hsel = kk & 1;
    int lane = gi * 4 + li;
    int reg = hi + 2 * khigh;
    long off = (long)seg * 131072
             + ((long)((m >> 7) * ntk + (k >> 5))) * 4096
             + (((ks * 8 + matom) * 32 + lane) * 4 + reg) * 2 + hsel;
    g_wh[off] = __float2half_rn(v);
}

// ---------------------------------------------------------------------------
// Kernel 1: depthwise 3x3 conv + BN; one thread = channel-pair x 4 pixels.
// ---------------------------------------------------------------------------
__global__ __launch_bounds__(256) void dwbn_kernel(const float* __restrict__ x,
    const float* __restrict__ qdw, const float* __restrict__ qg,
    const float* __restrict__ qb,  const float* __restrict__ qm,
    const float* __restrict__ qv,
    const float* __restrict__ kdw, const float* __restrict__ kg,
    const float* __restrict__ kb,  const float* __restrict__ km,
    const float* __restrict__ kv,
    const float* __restrict__ vdw, const float* __restrict__ vg,
    const float* __restrict__ vb,  const float* __restrict__ vm,
    const float* __restrict__ vv)
{
    const int NSTRIP = NPIX / 4;   // 784
    const int C2 = DIMC / 2;       // 128
    int idx = blockIdx.x * blockDim.x + threadIdx.x;
    if (idx >= BATCH * C2 * NSTRIP) return;
    int s = idx % NSTRIP;
    int c2 = (idx / NSTRIP) % C2;
    int b = idx / (NSTRIP * C2);
    int p0 = s * 4;
    int yy = p0 / HW, xx0 = p0 % HW;

    float oq[2][4], ok[2][4], ov[2][4];

    #pragma unroll
    for (int ch = 0; ch < 2; ch++) {
        int c = c2 * 2 + ch;
        float wq[9], wk[9], wv[9];
        #pragma unroll
        for (int t = 0; t < 9; t++) {
            wq[t] = __ldg(&qdw[c * 9 + t]);
            wk[t] = __ldg(&kdw[c * 9 + t]);
            wv[t] = __ldg(&vdw[c * 9 + t]);
        }
        const float* xb = x + ((long)(b * DIMC + c)) * NPIX;
        float aq[4] = {0.f, 0.f, 0.f, 0.f};
        float ak[4] = {0.f, 0.f, 0.f, 0.f};
        float av[4] = {0.f, 0.f, 0.f, 0.f};
        #pragma unroll
        for (int ky = 0; ky < 3; ky++) {
            int iy = yy + ky - 1;
            if (iy < 0 || iy >= HW) continue;
            const float* row = xb + iy * HW;
            float v[6];
            v[0] = (xx0 > 0) ? row[xx0 - 1] : 0.f;
            float4 mid = *(const float4*)&row[xx0];
            v[1] = mid.x; v[2] = mid.y; v[3] = mid.z; v[4] = mid.w;
            v[5] = (xx0 + 4 < HW) ? row[xx0 + 4] : 0.f;
            #pragma unroll
            for (int px = 0; px < 4; px++) {
                #pragma unroll
                for (int kx = 0; kx < 3; kx++) {
                    float xv = v[px + kx];
                    aq[px] += xv * wq[ky * 3 + kx];
                    ak[px] += xv * wk[ky * 3 + kx];
                    av[px] += xv * wv[ky * 3 + kx];
                }
            }
        }
        float sq = __ldg(&qg[c]) * rsqrtf(__ldg(&qv[c]) + 1e-5f);
        float sk = __ldg(&kg[c]) * rsqrtf(__ldg(&kv[c]) + 1e-5f);
        float sv = __ldg(&vg[c]) * rsqrtf(__ldg(&vv[c]) + 1e-5f);
        float mq = __ldg(&qm[c]), bq = __ldg(&qb[c]);
        float mk = __ldg(&km[c]), bk = __ldg(&kb[c]);
        float mv = __ldg(&vm[c]), bv = __ldg(&vb[c]);
        #pragma unroll
        for (int px = 0; px < 4; px++) {
            oq[ch][px] = (aq[px] - mq) * sq + bq;
            ok[ch][px] = (ak[px] - mk) * sk + bk;
            ov[ch][px] = (av[px] - mv) * sv + bv;
        }
    }

    const long PLANE_W = (long)BATCH * C2 * NPIX;
    long woff = ((long)(b * C2 + c2)) * NPIX + p0;
    uint32_t* gw = (uint32_t*)g_yh;
    uint4 pq, pk, pv;
    uint32_t* pqw = (uint32_t*)&pq;
    uint32_t* pkw = (uint32_t*)&pk;
    uint32_t* pvw = (uint32_t*)&pv;
    #pragma unroll
    for (int px = 0; px < 4; px++) {
        __half2 hq = __halves2half2(__float2half_rn(oq[0][px]), __float2half_rn(oq[1][px]));
        __half2 hk = __halves2half2(__float2half_rn(ok[0][px]), __float2half_rn(ok[1][px]));
        __half2 hv = __halves2half2(__float2half_rn(ov[0][px]), __float2half_rn(ov[1][px]));
        pqw[px] = *(uint32_t*)&hq;
        pkw[px] = *(uint32_t*)&hk;
        pvw[px] = *(uint32_t*)&hv;
    }
    *(uint4*)&gw[woff]               = pq;
    *(uint4*)&gw[PLANE_W + woff]     = pk;
    *(uint4*)&gw[2 * PLANE_W + woff] = pv;
}

// ---------------------------------------------------------------------------
// Kernel 2: qkv GEMM (fp16) with smem-transposed COALESCED windowed epilogue.
// grid: (25, 4, 48)
// ---------------------------------------------------------------------------
__global__ __launch_bounds__(256) void gemm_qkv_kernel()
{
    extern __shared__ __align__(16) uint32_t smemw[];
    uint32_t* smA = smemw;
    uint32_t* smB = smemw + NSTAGE * A_W2;

    int z = blockIdx.z;
    int proj = z >> 4;
    int b = z & 15;
    const __half* A = g_wh + (long)proj * 131072;
    const __half* B = g_yh + ((long)proj * BATCH + b) * DIMC * NPIX;

    int m0 = blockIdx.y * 128;
    int n0 = blockIdx.x * 128;

    float4 acc[4][4];
    gemm_core_h(A, B, DIMC, m0, n0, smA, smB, acc);

    const int lane = threadIdx.x & 31, warp = threadIdx.x >> 5;
    const int wm = warp >> 2, wn = warp & 3;
    const int gid = lane >> 2, tig = lane & 3;

    // stage C tile as fp16, pixel-major: Cs[p][128 ch], stride 132 halves
    __syncthreads();
    __half* Cs = (__half*)smemw;
    #pragma unroll
    for (int i = 0; i < 4; i++) {
        int clo = wm * 64 + i * 16 + gid;
        int chi = clo + 8;
        #pragma unroll
        for (int j = 0; j < 4; j++) {
            int pl = wn * 32 + j * 8 + tig * 2;
            Cs[(pl    ) * 132 + clo] = __float2half_rn(acc[i][j].x);
            Cs[(pl + 1) * 132 + clo] = __float2half_rn(acc[i][j].y);
            Cs[(pl    ) * 132 + chi] = __float2half_rn(acc[i][j].z);
            Cs[(pl + 1) * 132 + chi] = __float2half_rn(acc[i][j].w);
        }
    }
    __syncthreads();

    // coalesced store: 256 runs (128 pixels x 2 heads), each = 128B STG.32
    const uint32_t* Cw = (const uint32_t*)Cs;
    uint32_t* dstw = (uint32_t*)(g_qkvh + ((long)proj * BATCH + b) * HEADS * NWIN * NPIX);
    int h0 = m0 >> 6;
    #pragma unroll 4
    for (int r = warp; r < 256; r += 8) {
        int pl = r >> 1, hs = r & 1;
        int p = n0 + pl;
        if (p < NPIX) {
            int yy = p / HW, xx = p % HW;
            int w = (yy / WS) * 8 + (xx / WS);
            int t = (yy % WS) * WS + (xx % WS);
            uint32_t v = Cw[pl * 66 + hs * 32 + lane];
            dstw[(long)((h0 + hs) * NWIN + w) * (NPIX / 2) + t * 32 + lane] = v;
        }
    }
}

// ---------------------------------------------------------------------------
// Kernel 3: windowed attention, fp16; phase-2 B via ldmatrix.x4.trans.
// grid: (NWIN, HEADS, BATCH)
// ---------------------------------------------------------------------------
__global__ __launch_bounds__(128) void attn_kernel(const float* __restrict__ pos_emb)
{
    __shared__ __align__(16) uint32_t Qs[64 * QST2];   // aliased as Ps
    __shared__ __align__(16) uint32_t Ks[56 * QST2];
    __shared__ __align__(16) uint32_t Vs[50 * VSTW];   // rows 0..48 used
    __shared__ float p48s[64];
    uint32_t* Ps = Qs;

    int w = blockIdx.x, h = blockIdx.y, b = blockIdx.z;
    int tid = threadIdx.x;
    int lane = tid & 31, warp = tid >> 5;
    int gi = lane >> 2, li = lane & 3;

    const long PSTR = (long)BATCH * INNER * NPIX;
    long qbase = (((long)b * HEADS + h) * NWIN + w) * NPIX;
    const __half* gq = g_qkvh + qbase;
    const __half* gk = g_qkvh + PSTR + qbase;
    const __half* gv = g_qkvh + 2 * PSTR + qbase;

    uint32_t sQ = (uint32_t)__cvta_generic_to_shared(Qs);
    uint32_t sK = (uint32_t)__cvta_generic_to_shared(Ks);
    uint32_t sV = (uint32_t)__cvta_generic_to_shared(Vs);

    for (int i = tid; i < 7 * QST2; i += 128) {
        int t = NTOK + i / QST2, d = i % QST2;
        Ks[t * QST2 + d] = 0;
    }
    for (int i = tid; i < NTOK * 8; i += 128) {
        int t = i >> 3, c = i & 7;
        cpa16(sQ + (t * QST2) * 4 + c * 16, gq + t * 64 + c * 8);
        cpa16(sK + (t * QST2) * 4 + c * 16, gk + t * 64 + c * 8);
    }
    asm volatile("cp.async.commit_group;\n" ::: "memory");
    for (int i = tid; i < NTOK * 8; i += 128) {
        int t = i >> 3, c = i & 7;
        cpa16(sV + (t * VSTW) * 4 + c * 16, gv + t * 64 + c * 8);
    }
    asm volatile("cp.async.commit_group;\n" ::: "memory");

    asm volatile("cp.async.wait_group 1;\n" ::: "memory");
    __syncthreads();

    int row_lo = warp * 16 + gi;
    int row_hi = row_lo + 8;

    // ---- phase 1: S = Q K^T ----
    uint32_t a[4][4];
    #pragma unroll
    for (int ks = 0; ks < 4; ks++) {
        a[ks][0] = Qs[row_lo * QST2 + ks * 8 + li];
        a[ks][1] = Qs[row_hi * QST2 + ks * 8 + li];
        a[ks][2] = Qs[row_lo * QST2 + ks * 8 + li + 4];
        a[ks][3] = Qs[row_hi * QST2 + ks * 8 + li + 4];
    }
    float4 c[7];
    #pragma unroll
    for (int j = 0; j < 7; j++) {
        c[j] = make_float4(0.f, 0.f, 0.f, 0.f);
        #pragma unroll
        for (int ks = 0; ks < 4; ks++) {
            uint32_t b0 = Ks[(j * 8 + gi) * QST2 + ks * 8 + li];
            uint32_t b1 = Ks[(j * 8 + gi) * QST2 + ks * 8 + li + 4];
            mma_f16(c[j], a[ks][0], a[ks][1], a[ks][2], a[ks][3], b0, b1, c[j]);
        }
    }

    // ---- bias + softmax in registers ----
    int rr_lo = row_lo / 7, rc_lo = row_lo % 7;
    int rr_hi = row_hi / 7, rc_hi = row_hi % 7;
    float vlo[14], vhi[14];
    #pragma unroll
    for (int j = 0; j < 7; j++) {
        #pragma unroll
        for (int e = 0; e < 2; e++) {
            int col = j * 8 + li * 2 + e;
            float s_lo = (e == 0) ? c[j].x : c[j].y;
            float s_hi = (e == 0) ? c[j].z : c[j].w;
            if (col < NTOK) {
                int cr = col / 7, cc = col % 7;
                int rel_lo = (cr - rr_lo + 6) * 13 + (cc - rc_lo + 6);
                int rel_hi = (cr - rr_hi + 6) * 13 + (cc - rc_hi + 6);
                rel_lo = min(max(rel_lo, 0), 168);
                rel_hi = min(max(rel_hi, 0), 168);
                vlo[j * 2 + e] = fmaf(s_lo, 0.125f, __ldg(&pos_emb[rel_lo * HEADS + h]));
                vhi[j * 2 + e] = fmaf(s_hi, 0.125f, __ldg(&pos_emb[rel_hi * HEADS + h]));
            } else {
                vlo[j * 2 + e] = -1e30f;
                vhi[j * 2 + e] = -1e30f;
            }
        }
    }
    float mlo = -1e30f, mhi = -1e30f;
    #pragma unroll
    for (int i = 0; i < 14; i++) { mlo = fmaxf(mlo, vlo[i]); mhi = fmaxf(mhi, vhi[i]); }
    mlo = fmaxf(mlo, __shfl_xor_sync(0xffffffffu, mlo, 1));
    mlo = fmaxf(mlo, __shfl_xor_sync(0xffffffffu, mlo, 2));
    mhi = fmaxf(mhi, __shfl_xor_sync(0xffffffffu, mhi, 1));
    mhi = fmaxf(mhi, __shfl_xor_sync(0xffffffffu, mhi, 2));
    float slo = 0.f, shi = 0.f;
    #pragma unroll
    for (int i = 0; i < 14; i++) {
        vlo[i] = __expf(vlo[i] - mlo); slo += vlo[i];
        vhi[i] = __expf(vhi[i] - mhi); shi += vhi[i];
    }
    slo += __shfl_xor_sync(0xffffffffu, slo, 1);
    slo += __shfl_xor_sync(0xffffffffu, slo, 2);
    shi += __shfl_xor_sync(0xffffffffu, shi, 1);
    shi += __shfl_xor_sync(0xffffffffu, shi, 2);
    float ilo = 1.f / slo, ihi = 1.f / shi;

    asm volatile("cp.async.wait_group 0;\n" ::: "memory");
    __syncthreads();

    #pragma unroll
    for (int j = 0; j < 6; j++) {
        __half2 hlo = __halves2half2(__float2half_rn(vlo[j * 2] * ilo),
                                     __float2half_rn(vlo[j * 2 + 1] * ilo));
        __half2 hhi = __halves2half2(__float2half_rn(vhi[j * 2] * ihi),
                                     __float2half_rn(vhi[j * 2 + 1] * ihi));
        Ps[row_lo * QST2 + j * 4 + li] = *(uint32_t*)&hlo;
        Ps[row_hi * QST2 + j * 4 + li] = *(uint32_t*)&hhi;
    }
    if (li == 0) {
        p48s[row_lo] = vlo[12] * ilo;
        p48s[row_hi] = vhi[12] * ihi;
    }
    __syncthreads();

    // ---- phase 2: O = P V ----
    uint32_t pa[3][4];
    #pragma unroll
    for (int ks = 0; ks < 3; ks++) {
        pa[ks][0] = Ps[row_lo * QST2 + ks * 8 + li];
        pa[ks][1] = Ps[row_hi * QST2 + ks * 8 + li];
        pa[ks][2] = Ps[row_lo * QST2 + ks * 8 + li + 4];
        pa[ks][3] = Ps[row_hi * QST2 + ks * 8 + li + 4];
    }
    float pl48 = p48s[row_lo], ph48 = p48s[row_hi];
    const __half* Vh = (const __half*)Vs;

    uint32_t* gaw = (uint32_t*)g_ah;
    long wbase = (long)b * (INNER / 2) * NPIX + (long)w * NTOK;

    #pragma unroll
    for (int dblk = 0; dblk < 4; dblk++) {
        float4 oA = make_float4(0.f, 0.f, 0.f, 0.f);
        float4 oB = make_float4(0.f, 0.f, 0.f, 0.f);
        #pragma unroll
        for (int ks = 0; ks < 3; ks++) {
            int tRow = ks * 16 + (lane & 15);
            int dcol = dblk * 16 + ((lane >> 4) << 3);
            uint32_t addr = sV + (tRow * VSTW) * 4 + dcol * 2;
            uint32_t r0, r1, r2, r3;
            asm volatile(
                "ldmatrix.sync.aligned.m8n8.x4.trans.shared.b16 {%0,%1,%2,%3}, [%4];\n"
                : "=r"(r0), "=r"(r1), "=r"(r2), "=r"(r3) : "r"(addr));
            mma_f16(oA, pa[ks][0], pa[ks][1], pa[ks][2], pa[ks][3], r0, r1, oA);
            mma_f16(oB, pa[ks][0], pa[ks][1], pa[ks][2], pa[ks][3], r2, r3, oB);
        }
        #pragma unroll
        for (int half = 0; half < 2; half++) {
            float4 o = half ? oB : oA;
            int dn = dblk * 2 + half;
            int d0 = dn * 8 + 2 * li;
            float v48a = __half2float(Vh[48 * (VSTW * 2) + d0]);
            float v48b = __half2float(Vh[48 * (VSTW * 2) + d0 + 1]);
            o.x += pl48 * v48a;  o.y += pl48 * v48b;
            o.z += ph48 * v48a;  o.w += ph48 * v48b;

            long cw = ((long)(h * 64 + d0) >> 1) * NPIX;
            if (row_lo < NTOK) {
                __half2 hv = __halves2half2(__float2half_rn(o.x), __float2half_rn(o.y));
                gaw[wbase + cw + row_lo] = *(uint32_t*)&hv;
            }
            if (row_hi < NTOK) {
                __half2 hv = __halves2half2(__float2half_rn(o.z), __float2half_rn(o.w));
                gaw[wbase + cw + row_hi] = *(uint32_t*)&hv;
            }
        }
    }
}

// ---------------------------------------------------------------------------
// Kernel 4: out-projection GEMM (fp16) + bias, un-window on store
// grid: (25, 2, 16)
// ---------------------------------------------------------------------------
__global__ __launch_bounds__(256) void gemm_out_kernel(
    const float* __restrict__ ob, float* __restrict__ out)
{
    extern __shared__ __align__(16) uint32_t smemw[];
    uint32_t* smA = smemw;
    uint32_t* smB = smemw + NSTAGE * A_W2;

    int b = blockIdx.z;
    const __half* A = g_wh + 3L * 131072;
    const __half* B = g_ah + (long)b * INNER * NPIX;

    int m0 = blockIdx.y * 128;
    int n0 = blockIdx.x * 128;

    float4 acc[4][4];
    gemm_core_h(A, B, INNER, m0, n0, smA, smB, acc);

    const int lane = threadIdx.x & 31, warp = threadIdx.x >> 5;
    const int wm = warp >> 2, wn = warp & 3;
    const int gid = lane >> 2, tig = lane & 3;

    #pragma unroll
    for (int i = 0; i < 4; i++) {
        int o_lo = m0 + wm * 64 + i * 16 + gid;
        int o_hi = o_lo + 8;
        float bias_lo = __ldg(&ob[o_lo]);
        float bias_hi = __ldg(&ob[o_hi]);
        #pragma unroll
        for (int j = 0; j < 4; j++) {
            int p0 = n0 + wn * 32 + j * 8 + tig * 2;
            int p1 = p0 + 1;
            float vals[4] = {acc[i][j].x + bias_lo, acc[i][j].y + bias_lo,
                             acc[i][j].z + bias_hi, acc[i][j].w + bias_hi};
            int os[4] = {o_lo, o_lo, o_hi, o_hi};
            int ps[4] = {p0, p1, p0, p1};
            #pragma unroll
            for (int e = 0; e < 4; e++) {
                int p = ps[e];
                if (p < NPIX) {
                    int o = os[e];
                    int w = p / NTOK, t = p % NTOK;
                    int yy = (w / 8) * WS + t / WS;
                    int xx = (w % 8) * WS + t % WS;
                    out[((long)b * DIMC + o) * NPIX + yy * HW + xx] = vals[e];
                }
            }
        }
    }
}

// ---------------------------------------------------------------------------
extern "C" void kernel_launch(void* const* d_in, const int* in_sizes, int n_in,
                              void* d_out, int out_size)
{
    const float* x    = (const float*)d_in[0];
    const float* qdw  = (const float*)d_in[1];
    const float* qg   = (const float*)d_in[2];
    const float* qb   = (const float*)d_in[3];
    const float* qm   = (const float*)d_in[4];
    const float* qv   = (const float*)d_in[5];
    const float* qpw  = (const float*)d_in[6];
    const float* kdw  = (const float*)d_in[7];
    const float* kg   = (const float*)d_in[8];
    const float* kb   = (const float*)d_in[9];
    const float* km   = (const float*)d_in[10];
    const float* kv   = (const float*)d_in[11];
    const float* kpw  = (const float*)d_in[12];
    const float* vdw  = (const float*)d_in[13];
    const float* vg   = (const float*)d_in[14];
    const float* vb   = (const float*)d_in[15];
    const float* vm   = (const float*)d_in[16];
    const float* vv   = (const float*)d_in[17];
    const float* vpw  = (const float*)d_in[18];
    const float* pos  = (const float*)d_in[19];
    const float* outw = (const float*)d_in[20];
    const float* outb = (const float*)d_in[21];
    float* out = (float*)d_out;

    static bool attr_done = false;
    if (!attr_done) {
        cudaFuncSetAttribute(gemm_qkv_kernel,
            cudaFuncAttributeMaxDynamicSharedMemorySize, GEMM_SMEM_BYTES);
        cudaFuncSetAttribute(gemm_out_kernel,
            cudaFuncAttributeMaxDynamicSharedMemorySize, GEMM_SMEM_BYTES);
        attr_done = true;
    }

    prep_w_kernel<<<2048, 256>>>(qpw, kpw, vpw, outw);

    int npair = BATCH * (DIMC / 2) * (NPIX / 4);
    dwbn_kernel<<<(npair + 255) / 256, 256>>>(x,
        qdw, qg, qb, qm, qv,
        kdw, kg, kb, km, kv,
        vdw, vg, vb, vm, vv);

    gemm_qkv_kernel<<<dim3(25, 4, 48), 256, GEMM_SMEM_BYTES>>>();

    attn_kernel<<<dim3(NWIN, HEADS, BATCH), 128>>>(pos);

    gemm_out_kernel<<<dim3(25, 2, 16), 256, GEMM_SMEM_BYTES>>>(outb, out);
}